// round 11
// baseline (speedup 1.0000x reference)
#include <cuda_runtime.h>
#include <cuda_fp16.h>
#include <cstdint>

// ---------------- problem constants ----------------
#define B_ 2
#define T_ 2048
#define DIM_ 1024
#define SEG_ 8
#define SD_ 128
#define NE_ 16
#define KTOP_ 2
#define HSH_ 4096
#define HR_ 512
#define TOK_ (B_ * T_)            // 4096 tokens
#define NS_ (TOK_ * SEG_)         // 32768 token-segments
#define NENT_ (NS_ * KTOP_)       // 65536 routed entries

// ---------------- device scratch ----------------
__device__ __half g_Xc[TOK_ * DIM_];
__device__ __half g_W1c[DIM_ * HSH_];
__device__ __half g_W2c[HSH_ * DIM_];
__device__ __half g_H1c[TOK_ * HSH_];
__device__ __half g_E1c[NE_ * SD_ * HR_];
__device__ __half g_E2c[NE_ * HR_ * SD_];
__device__ float g_Yent[NENT_ * SD_];
__device__ int   g_top_idx[NENT_];
__device__ float g_top_w[NENT_];
__device__ int   g_cnt[NE_];
__device__ float g_wsum[NE_];
__device__ int   g_off[NE_ + 1];
__device__ int   g_cursor[NE_];
__device__ int   g_perm[NENT_];

__device__ __forceinline__ float gelu_t(float x) {
    float x3 = x * x * x;
    return 0.5f * x * (1.0f + tanhf(0.7978845608028654f * (x + 0.044715f * x3)));
}

__device__ __forceinline__ uint32_t smem_u32(const void* p) {
    uint32_t a;
    asm("{ .reg .u64 t; cvta.to.shared.u64 t, %1; cvt.u32.u64 %0, t; }" : "=r"(a) : "l"(p));
    return a;
}

__device__ __forceinline__ void ldsm_x4(uint32_t r[4], uint32_t addr) {
    asm volatile("ldmatrix.sync.aligned.m8n8.x4.shared.b16 {%0,%1,%2,%3}, [%4];"
        : "=r"(r[0]), "=r"(r[1]), "=r"(r[2]), "=r"(r[3]) : "r"(addr));
}
__device__ __forceinline__ void ldsm_x4_t(uint32_t r[4], uint32_t addr) {
    asm volatile("ldmatrix.sync.aligned.m8n8.x4.trans.shared.b16 {%0,%1,%2,%3}, [%4];"
        : "=r"(r[0]), "=r"(r[1]), "=r"(r[2]), "=r"(r[3]) : "r"(addr));
}
__device__ __forceinline__ void mma_f16(float d[4], const uint32_t a[4], const uint32_t b[2]) {
    asm volatile("mma.sync.aligned.m16n8k16.row.col.f32.f16.f16.f32 "
        "{%0,%1,%2,%3}, {%4,%5,%6,%7}, {%8,%9}, {%0,%1,%2,%3};"
        : "+f"(d[0]), "+f"(d[1]), "+f"(d[2]), "+f"(d[3])
        : "r"(a[0]), "r"(a[1]), "r"(a[2]), "r"(a[3]), "r"(b[0]), "r"(b[1]));
}
__device__ __forceinline__ void cp16(uint32_t s, const void* g, int szbytes) {
    asm volatile("cp.async.cg.shared.global [%0], [%1], 16, %2;"
        :: "r"(s), "l"(g), "r"(szbytes));
}
__device__ __forceinline__ void cp_commit() { asm volatile("cp.async.commit_group;" ::: "memory"); }
__device__ __forceinline__ void cp_wait0()  { asm volatile("cp.async.wait_group 0;" ::: "memory"); }
__device__ __forceinline__ void cp_wait1()  { asm volatile("cp.async.wait_group 1;" ::: "memory"); }

// ---------------- fp32 -> fp16 conversion ----------------
__global__ void cvt_kernel(const float* __restrict__ src, __half* __restrict__ dst, int n4) {
    int i = blockIdx.x * 256 + threadIdx.x;
    if (i >= n4) return;
    float4 v = ((const float4*)src)[i];
    ((__half2*)dst)[2 * i]     = __floats2half2_rn(v.x, v.y);
    ((__half2*)dst)[2 * i + 1] = __floats2half2_rn(v.z, v.w);
}

__global__ void cvt2_kernel(const float* __restrict__ s1, __half* __restrict__ d1, int n1,
                            const float* __restrict__ s2, __half* __restrict__ d2, int n2) {
    int i = blockIdx.x * 256 + threadIdx.x;
    const float* s; __half* d; int j;
    if (i < n1) { s = s1; d = d1; j = i; }
    else if (i < n1 + n2) { s = s2; d = d2; j = i - n1; }
    else return;
    float4 v = ((const float4*)s)[j];
    ((__half2*)d)[2 * j]     = __floats2half2_rn(v.x, v.y);
    ((__half2*)d)[2 * j + 1] = __floats2half2_rn(v.z, v.w);
}

// ---------------- HMMA fp16 GEMM, 3-stage cp.async pipeline ----------------
// MODE 0: epilogue gelu(acc+bias) -> Ch fp16
// MODE 1: epilogue acc+bias + routed combine (reads g_Yent) -> Cf fp32
#define BM_ 128
#define BN_ 128
#define BK_ 64
#define ASTR_ 72
#define BSTR_ 136
#define STG_BYTES 35840
#define GSM_BYTES (3 * STG_BYTES)

template <int MODE>
__global__ void __launch_bounds__(256, 2)
gemm_hmma(const __half* __restrict__ A, const __half* __restrict__ Bm,
          const float* __restrict__ bias,
          float* __restrict__ Cf, __half* __restrict__ Ch,
          int M, int N, int K) {
    extern __shared__ char smraw[];

    int tid = threadIdx.x;
    int wid = tid >> 5, lane = tid & 31;
    int wm = wid & 1, wn = wid >> 1;
    int bn = blockIdx.x * BN_, bm = blockIdx.y * BM_;

    uint32_t uS = smem_u32(smraw);

    float acc[4][4][4];
#pragma unroll
    for (int i = 0; i < 4; i++)
#pragma unroll
        for (int j = 0; j < 4; j++)
#pragma unroll
            for (int q = 0; q < 4; q++) acc[i][j][q] = 0.0f;

    int lo16 = lane & 15, hi16 = lane >> 4;

    auto load_chunk = [&](int kc, int st) {
        uint32_t bA = uS + st * STG_BYTES;
        uint32_t bB = bA + 18432;
#pragma unroll 2
        for (int i = tid; i < 1024; i += 256) {
            int r = i >> 3, u = i & 7;
            int g = (bm + r) * K + kc + u * 8;
            cp16(bA + (uint32_t)(r * ASTR_ + u * 8) * 2, A + g, 16);
        }
#pragma unroll 2
        for (int i = tid; i < 1024; i += 256) {
            int r = i >> 4, u = i & 15;
            int g = (kc + r) * N + bn + u * 8;
            cp16(bB + (uint32_t)(r * BSTR_ + u * 8) * 2, Bm + g, 16);
        }
    };

    int nch = K / BK_;
    load_chunk(0, 0);
    cp_commit();
    load_chunk(BK_, 1);
    cp_commit();

    for (int c = 0; c < nch; c++) {
        int st = c % 3;
        cp_wait1();
        __syncthreads();
        if (c + 2 < nch) load_chunk((c + 2) * BK_, (c + 2) % 3);
        cp_commit();

        uint32_t uA = uS + st * STG_BYTES;
        uint32_t uB = uA + 18432;

#pragma unroll
        for (int ks = 0; ks < 4; ks++) {
            int k0 = ks * 16;
            uint32_t Bf[4][2];
#pragma unroll
            for (int p = 0; p < 2; p++) {
                uint32_t boff = (uint32_t)(((k0 + lo16) * BSTR_ + wn * 32 + p * 16 + 8 * hi16) * 2);
                uint32_t r4[4];
                ldsm_x4_t(r4, uB + boff);
                Bf[p * 2][0] = r4[0]; Bf[p * 2][1] = r4[1];
                Bf[p * 2 + 1][0] = r4[2]; Bf[p * 2 + 1][1] = r4[3];
            }
            uint32_t Af[4][4];
#pragma unroll
            for (int mt = 0; mt < 4; mt++) {
                uint32_t aoff = (uint32_t)(((wm * 64 + mt * 16 + lo16) * ASTR_ + k0 + 8 * hi16) * 2);
                ldsm_x4(Af[mt], uA + aoff);
            }
#pragma unroll
            for (int mt = 0; mt < 4; mt++)
#pragma unroll
                for (int nt = 0; nt < 4; nt++) mma_f16(acc[mt][nt], Af[mt], Bf[nt]);
        }
    }

    int row_in = lane >> 2, colq = (lane & 3) * 2;
#pragma unroll
    for (int mt = 0; mt < 4; mt++) {
#pragma unroll
        for (int nt = 0; nt < 4; nt++) {
            int m0 = bm + wm * 64 + mt * 16 + row_in;
            int n0 = bn + wn * 32 + nt * 8 + colq;
            float b0 = bias[n0], b1 = bias[n0 + 1];
            float v00 = acc[mt][nt][0] + b0, v01 = acc[mt][nt][1] + b1;
            float v10 = acc[mt][nt][2] + b0, v11 = acc[mt][nt][3] + b1;
            if (MODE == 0) {
                *(__half2*)(Ch + m0 * N + n0)       = __floats2half2_rn(gelu_t(v00), gelu_t(v01));
                *(__half2*)(Ch + (m0 + 8) * N + n0) = __floats2half2_rn(gelu_t(v10), gelu_t(v11));
            } else {
                // fused routed combine: out = shared + sum_k w_k*y_k
                int s = n0 >> 7, c = n0 & 127;
                int slot0 = m0 * SEG_ + s;
                int slot1 = (m0 + 8) * SEG_ + s;
                const float* y00 = g_Yent + (2 * slot0) * SD_ + c;
                const float* y01 = g_Yent + (2 * slot0 + 1) * SD_ + c;
                const float* y10 = g_Yent + (2 * slot1) * SD_ + c;
                const float* y11 = g_Yent + (2 * slot1 + 1) * SD_ + c;
                float2 a0 = *(const float2*)y00, b0v = *(const float2*)y01;
                float2 a1 = *(const float2*)y10, b1v = *(const float2*)y11;
                *(float2*)(Cf + m0 * N + n0) =
                    make_float2(v00 + a0.x + b0v.x, v01 + a0.y + b0v.y);
                *(float2*)(Cf + (m0 + 8) * N + n0) =
                    make_float2(v10 + a1.x + b1v.x, v11 + a1.y + b1v.y);
            }
        }
    }
}

// ---------------- routed experts: fp16 single-pass, 512 threads ----------------
#define RT2_SMEM (44544 * 2)

__global__ void __launch_bounds__(512)
routed_hmma(const __half* __restrict__ Xc,
            const __half* __restrict__ E1c, const float* __restrict__ be1,
            const __half* __restrict__ E2c, const float* __restrict__ be2) {
    extern __shared__ __half sm2[];
    __shared__ int   s_entry[128];
    __shared__ float s_w[128];

    int tid = threadIdx.x, wid = tid >> 5, lane = tid & 31;
    int e = blockIdx.y;
    int base = g_off[e] + blockIdx.x * 128;
    int end  = g_off[e + 1];
    if (base >= end) return;

    __half* sH = sm2 + 17408;

    uint32_t uS  = smem_u32(sm2);
    uint32_t uX  = uS;
    uint32_t uH  = uS + 17408 * 2;
    uint32_t uW1 = uS + 26624 * 2;
    uint32_t uW2 = uS + 35840 * 2;

    for (int i = tid; i < 128; i += 512) {
        int p = base + i;
        if (p < end) {
            int en = g_perm[p];
            s_entry[i] = en;
            s_w[i] = g_top_w[en];
        } else {
            s_entry[i] = -1;
            s_w[i] = 0.0f;
        }
    }
    __syncthreads();

    const __half* W1 = E1c + e * (SD_ * HR_);
    const __half* W2 = E2c + e * (HR_ * SD_);
    const float* b1 = be1 + e * HR_;
    const float* b2 = be2 + e * SD_;

    for (int i = tid; i < 2048; i += 512) {
        int row = i >> 4, u = i & 15;
        int en = s_entry[row];
        int sz = (en >= 0) ? 16 : 0;
        int slot = en >> 1;
        long goff = (en >= 0) ? ((long)(slot >> 3) * DIM_ + (slot & 7) * SD_ + u * 8) : 0;
        cp16(uX + (uint32_t)(row * 136 + u * 8) * 2, Xc + goff, sz);
    }
    for (int i = tid; i < 1024; i += 512) {
        int k = i >> 3, u = i & 7;
        cp16(uW1 + (uint32_t)(k * 72 + u * 8) * 2, W1 + k * HR_ + u * 8, 16);
    }
    cp_commit();
    cp_wait0();
    __syncthreads();

    int wm = wid & 3, wn = wid >> 2;
    int lo16 = lane & 15, hi16 = lane >> 4;
    int row_in = lane >> 2, colq = (lane & 3) * 2;

    float yacc[2][4][4];
#pragma unroll
    for (int i = 0; i < 2; i++)
#pragma unroll
        for (int j = 0; j < 4; j++)
#pragma unroll
            for (int q = 0; q < 4; q++) yacc[i][j][q] = 0.0f;

    for (int ch = 0; ch < 8; ch++) {
        int h0 = ch * 64;

        for (int i = tid; i < 1024; i += 512) {
            int k = i >> 4, u = i & 15;
            cp16(uW2 + (uint32_t)(k * 136 + u * 8) * 2, W2 + (h0 + k) * SD_ + u * 8, 16);
        }
        cp_commit();

        float hacc[2][2][4];
#pragma unroll
        for (int i = 0; i < 2; i++)
#pragma unroll
            for (int j = 0; j < 2; j++)
#pragma unroll
                for (int q = 0; q < 4; q++) hacc[i][j][q] = 0.0f;

#pragma unroll
        for (int ks = 0; ks < 8; ks++) {
            int k0 = ks * 16;
            uint32_t boff = (uint32_t)(((k0 + lo16) * 72 + wn * 16 + 8 * hi16) * 2);
            uint32_t Bf[2][2], r4[4];
            ldsm_x4_t(r4, uW1 + boff);
            Bf[0][0] = r4[0]; Bf[0][1] = r4[1]; Bf[1][0] = r4[2]; Bf[1][1] = r4[3];
            uint32_t Af[2][4];
#pragma unroll
            for (int mt = 0; mt < 2; mt++) {
                uint32_t aoff = (uint32_t)(((wm * 32 + mt * 16 + lo16) * 136 + k0 + 8 * hi16) * 2);
                ldsm_x4(Af[mt], uX + aoff);
            }
#pragma unroll
            for (int mt = 0; mt < 2; mt++)
#pragma unroll
                for (int nt = 0; nt < 2; nt++) mma_f16(hacc[mt][nt], Af[mt], Bf[nt]);
        }

#pragma unroll
        for (int mt = 0; mt < 2; mt++) {
#pragma unroll
            for (int nt = 0; nt < 2; nt++) {
                int n0 = wn * 16 + nt * 8 + colq;
                float bb0 = b1[h0 + n0], bb1 = b1[h0 + n0 + 1];
                int r0 = wm * 32 + mt * 16 + row_in;
                *(__half2*)(sH + r0 * 72 + n0) =
                    __floats2half2_rn(gelu_t(hacc[mt][nt][0] + bb0), gelu_t(hacc[mt][nt][1] + bb1));
                *(__half2*)(sH + (r0 + 8) * 72 + n0) =
                    __floats2half2_rn(gelu_t(hacc[mt][nt][2] + bb0), gelu_t(hacc[mt][nt][3] + bb1));
            }
        }
        cp_wait0();
        __syncthreads();

        if (ch < 7) {
            int h1 = h0 + 64;
            for (int i = tid; i < 1024; i += 512) {
                int k = i >> 3, u = i & 7;
                cp16(uW1 + (uint32_t)(k * 72 + u * 8) * 2, W1 + k * HR_ + h1 + u * 8, 16);
            }
        }
        cp_commit();

#pragma unroll
        for (int ks = 0; ks < 4; ks++) {
            int k0 = ks * 16;
            uint32_t Bf[4][2];
#pragma unroll
            for (int p = 0; p < 2; p++) {
                uint32_t boff = (uint32_t)(((k0 + lo16) * 136 + wn * 32 + p * 16 + 8 * hi16) * 2);
                uint32_t r4[4];
                ldsm_x4_t(r4, uW2 + boff);
                Bf[p * 2][0] = r4[0]; Bf[p * 2][1] = r4[1];
                Bf[p * 2 + 1][0] = r4[2]; Bf[p * 2 + 1][1] = r4[3];
            }
            uint32_t Af[2][4];
#pragma unroll
            for (int mt = 0; mt < 2; mt++) {
                uint32_t aoff = (uint32_t)(((wm * 32 + mt * 16 + lo16) * 72 + k0 + 8 * hi16) * 2);
                ldsm_x4(Af[mt], uH + aoff);
            }
#pragma unroll
            for (int mt = 0; mt < 2; mt++)
#pragma unroll
                for (int nt = 0; nt < 4; nt++) mma_f16(yacc[mt][nt], Af[mt], Bf[nt]);
        }
        cp_wait0();
        __syncthreads();
    }

#pragma unroll
    for (int mt = 0; mt < 2; mt++) {
#pragma unroll
        for (int nt = 0; nt < 4; nt++) {
            int n0 = wn * 32 + nt * 8 + colq;
            float bb0 = b2[n0], bb1 = b2[n0 + 1];
            int r0 = wm * 32 + mt * 16 + row_in;
            int en0 = s_entry[r0];
            if (en0 >= 0) {
                float w = s_w[r0];
                *(float2*)(g_Yent + en0 * SD_ + n0) =
                    make_float2(w * (yacc[mt][nt][0] + bb0), w * (yacc[mt][nt][1] + bb1));
            }
            int en1 = s_entry[r0 + 8];
            if (en1 >= 0) {
                float w = s_w[r0 + 8];
                *(float2*)(g_Yent + en1 * SD_ + n0) =
                    make_float2(w * (yacc[mt][nt][2] + bb0), w * (yacc[mt][nt][3] + bb1));
            }
        }
    }
}

// ---------------- init ----------------
__global__ void init_kernel() {
    int t = threadIdx.x;
    if (t < NE_) { g_cnt[t] = 0; g_wsum[t] = 0.0f; }
}

// ---------------- router ----------------
__global__ void router_kernel(const float* __restrict__ X, const float* __restrict__ Wr) {
    __shared__ float Wrs[SD_ * NE_];
    __shared__ int   scnt[NE_];
    __shared__ float sws[NE_];
    int tid = threadIdx.x;
    for (int i = tid; i < SD_ * NE_; i += 128) Wrs[i] = Wr[i];
    if (tid < NE_) { scnt[tid] = 0; sws[tid] = 0.0f; }
    __syncthreads();

    int slot = blockIdx.x * 128 + tid;
    const float* x = X + (slot >> 3) * DIM_ + (slot & 7) * SD_;
    float lg[NE_];
#pragma unroll
    for (int e = 0; e < NE_; e++) lg[e] = 0.0f;
    for (int k = 0; k < SD_; k++) {
        float xv = x[k];
        const float* wr = &Wrs[k * NE_];
#pragma unroll
        for (int e = 0; e < NE_; e++) lg[e] += xv * wr[e];
    }
    float mx = lg[0];
#pragma unroll
    for (int e = 1; e < NE_; e++) mx = fmaxf(mx, lg[e]);
    float p[NE_]; float sum = 0.0f;
#pragma unroll
    for (int e = 0; e < NE_; e++) { p[e] = expf(lg[e] - mx); sum += p[e]; }
    float inv = 1.0f / sum;
    int i0 = 0; float m0 = -1.0f;
#pragma unroll
    for (int e = 0; e < NE_; e++) if (p[e] > m0) { m0 = p[e]; i0 = e; }
    int i1 = 0; float m1 = -1.0f;
#pragma unroll
    for (int e = 0; e < NE_; e++) if (e != i0 && p[e] > m1) { m1 = p[e]; i1 = e; }
    float w0 = m0 * inv, w1 = m1 * inv;

    g_top_idx[2 * slot]     = i0;
    g_top_idx[2 * slot + 1] = i1;
    g_top_w[2 * slot]       = w0;
    g_top_w[2 * slot + 1]   = w1;

    atomicAdd(&scnt[i0], 1); atomicAdd(&scnt[i1], 1);
    atomicAdd(&sws[i0], w0); atomicAdd(&sws[i1], w1);
    __syncthreads();
    if (tid < NE_) {
        atomicAdd(&g_cnt[tid], scnt[tid]);
        atomicAdd(&g_wsum[tid], sws[tid]);
    }
}

// ---------------- offsets + aux (writes aux straight into out) ----------------
__global__ void offsets_kernel(float* __restrict__ out, int out_size) {
    if (threadIdx.x == 0) {
        int acc = 0; float aux = 0.0f;
        for (int e = 0; e < NE_; e++) {
            g_off[e] = acc; g_cursor[e] = acc;
            acc += g_cnt[e];
            float f = (float)g_cnt[e] / ((float)NS_ * (float)KTOP_);
            float P = g_wsum[e] / (float)NS_;
            aux += f * P;
        }
        g_off[NE_] = acc;
        if (out_size > TOK_ * DIM_) out[TOK_ * DIM_] = (float)NE_ * aux;
    }
}

// ---------------- scatter ----------------
__global__ void scatter_kernel() {
    int slot = blockIdx.x * blockDim.x + threadIdx.x;
    if (slot >= NS_) return;
#pragma unroll
    for (int k = 0; k < KTOP_; k++) {
        int en = 2 * slot + k;
        int e = g_top_idx[en];
        int p = atomicAdd(&g_cursor[e], 1);
        g_perm[p] = en;
    }
}

// ---------------- launch ----------------
extern "C" void kernel_launch(void* const* d_in, const int* in_sizes, int n_in,
                              void* d_out, int out_size) {
    const float* X   = (const float*)d_in[0];
    const float* Ws1 = (const float*)d_in[1];
    const float* bs1 = (const float*)d_in[2];
    const float* Ws2 = (const float*)d_in[3];
    const float* bs2 = (const float*)d_in[4];
    const float* Wr  = (const float*)d_in[5];
    const float* We1 = (const float*)d_in[6];
    const float* be1 = (const float*)d_in[7];
    const float* We2 = (const float*)d_in[8];
    const float* be2 = (const float*)d_in[9];
    float* out = (float*)d_out;

    static cudaStream_t s2 = nullptr, s3 = nullptr;
    static cudaEvent_t evStart = nullptr, evScatter = nullptr, evX = nullptr;
    static cudaEvent_t evJoin = nullptr, evW2 = nullptr;
    if (s2 == nullptr) {
        cudaStreamCreateWithFlags(&s2, cudaStreamNonBlocking);
        cudaStreamCreateWithFlags(&s3, cudaStreamNonBlocking);
        cudaEventCreateWithFlags(&evStart,   cudaEventDisableTiming);
        cudaEventCreateWithFlags(&evScatter, cudaEventDisableTiming);
        cudaEventCreateWithFlags(&evX,       cudaEventDisableTiming);
        cudaEventCreateWithFlags(&evJoin,    cudaEventDisableTiming);
        cudaEventCreateWithFlags(&evW2,      cudaEventDisableTiming);
    }

    cudaFuncSetAttribute(gemm_hmma<0>, cudaFuncAttributeMaxDynamicSharedMemorySize, GSM_BYTES);
    cudaFuncSetAttribute(gemm_hmma<1>, cudaFuncAttributeMaxDynamicSharedMemorySize, GSM_BYTES);
    cudaFuncSetAttribute(routed_hmma, cudaFuncAttributeMaxDynamicSharedMemorySize, RT2_SMEM);

    __half *Xc, *W1c, *W2c, *H1c, *E1c, *E2c;
    cudaGetSymbolAddress((void**)&Xc,  g_Xc);
    cudaGetSymbolAddress((void**)&W1c, g_W1c);
    cudaGetSymbolAddress((void**)&W2c, g_W2c);
    cudaGetSymbolAddress((void**)&H1c, g_H1c);
    cudaGetSymbolAddress((void**)&E1c, g_E1c);
    cudaGetSymbolAddress((void**)&E2c, g_E2c);

    // ---- fork: three streams ----
    cudaEventRecord(evStart, 0);
    cudaStreamWaitEvent(s2, evStart, 0);
    cudaStreamWaitEvent(s3, evStart, 0);

    // s3: router chain + W2 convert (all off the critical path)
    init_kernel<<<1, 64, 0, s3>>>();
    router_kernel<<<NS_ / 128, 128, 0, s3>>>(X, Wr);
    offsets_kernel<<<1, 32, 0, s3>>>(out, out_size);
    scatter_kernel<<<NS_ / 128, 128, 0, s3>>>();
    cudaEventRecord(evScatter, s3);
    cvt_kernel<<<(HSH_ * DIM_ / 4 + 255) / 256, 256, 0, s3>>>(Ws2, W2c, HSH_ * DIM_ / 4);
    cudaEventRecord(evW2, s3);

    // s2: routed prerequisites + routed
    cvt_kernel<<<(TOK_ * DIM_ / 4 + 255) / 256, 256, 0, s2>>>(X, Xc, TOK_ * DIM_ / 4);
    cudaEventRecord(evX, s2);
    cvt2_kernel<<<(NE_ * SD_ * HR_ / 4 + NE_ * HR_ * SD_ / 4 + 255) / 256, 256, 0, s2>>>(
        We1, E1c, NE_ * SD_ * HR_ / 4, We2, E2c, NE_ * HR_ * SD_ / 4);
    cudaStreamWaitEvent(s2, evScatter, 0);
    routed_hmma<<<dim3(NENT_ / 128, NE_), 512, RT2_SMEM, s2>>>(
        Xc, E1c, be1, E2c, be2);
    cudaEventRecord(evJoin, s2);

    // main: shared expert (critical path): cvt W1 -> gemm1 -> gemm2(+combine)
    cvt_kernel<<<(DIM_ * HSH_ / 4 + 255) / 256, 256>>>(Ws1, W1c, DIM_ * HSH_ / 4);
    cudaStreamWaitEvent(0, evX, 0);
    gemm_hmma<0><<<dim3(HSH_ / BN_, TOK_ / BM_), 256, GSM_BYTES>>>(
        Xc, W1c, bs1, nullptr, H1c, TOK_, HSH_, DIM_);
    cudaStreamWaitEvent(0, evW2, 0);
    cudaStreamWaitEvent(0, evJoin, 0);
    gemm_hmma<1><<<dim3(DIM_ / BN_, TOK_ / BM_), 256, GSM_BYTES>>>(
        H1c, W2c, bs2, out, nullptr, TOK_, DIM_, HSH_);
}

// round 12
// speedup vs baseline: 1.4100x; 1.4100x over previous
#include <cuda_runtime.h>
#include <cuda_fp16.h>
#include <cstdint>

// ---------------- problem constants ----------------
#define B_ 2
#define T_ 2048
#define DIM_ 1024
#define SEG_ 8
#define SD_ 128
#define NE_ 16
#define KTOP_ 2
#define HSH_ 4096
#define HR_ 512
#define TOK_ (B_ * T_)            // 4096 tokens
#define NS_ (TOK_ * SEG_)         // 32768 token-segments
#define NENT_ (NS_ * KTOP_)       // 65536 routed entries

// ---------------- device scratch ----------------
__device__ __half g_Xc[TOK_ * DIM_];
__device__ __half g_W1c[DIM_ * HSH_];
__device__ __half g_W2c[HSH_ * DIM_];
__device__ __half g_H1c[TOK_ * HSH_];
__device__ __half g_E1c[NE_ * SD_ * HR_];
__device__ __half g_E2c[NE_ * HR_ * SD_];
__device__ float g_Yent[NENT_ * SD_];
__device__ int   g_top_idx[NENT_];
__device__ float g_top_w[NENT_];
__device__ int   g_cnt[NE_];
__device__ float g_wsum[NE_];
__device__ int   g_off[NE_ + 1];
__device__ int   g_cursor[NE_];
__device__ int   g_perm[NENT_];

__device__ __forceinline__ float gelu_t(float x) {
    float x3 = x * x * x;
    return 0.5f * x * (1.0f + tanhf(0.7978845608028654f * (x + 0.044715f * x3)));
}

__device__ __forceinline__ uint32_t smem_u32(const void* p) {
    uint32_t a;
    asm("{ .reg .u64 t; cvta.to.shared.u64 t, %1; cvt.u32.u64 %0, t; }" : "=r"(a) : "l"(p));
    return a;
}

__device__ __forceinline__ void ldsm_x4(uint32_t r[4], uint32_t addr) {
    asm volatile("ldmatrix.sync.aligned.m8n8.x4.shared.b16 {%0,%1,%2,%3}, [%4];"
        : "=r"(r[0]), "=r"(r[1]), "=r"(r[2]), "=r"(r[3]) : "r"(addr));
}
__device__ __forceinline__ void ldsm_x4_t(uint32_t r[4], uint32_t addr) {
    asm volatile("ldmatrix.sync.aligned.m8n8.x4.trans.shared.b16 {%0,%1,%2,%3}, [%4];"
        : "=r"(r[0]), "=r"(r[1]), "=r"(r[2]), "=r"(r[3]) : "r"(addr));
}
__device__ __forceinline__ void mma_f16(float d[4], const uint32_t a[4], const uint32_t b[2]) {
    asm volatile("mma.sync.aligned.m16n8k16.row.col.f32.f16.f16.f32 "
        "{%0,%1,%2,%3}, {%4,%5,%6,%7}, {%8,%9}, {%0,%1,%2,%3};"
        : "+f"(d[0]), "+f"(d[1]), "+f"(d[2]), "+f"(d[3])
        : "r"(a[0]), "r"(a[1]), "r"(a[2]), "r"(a[3]), "r"(b[0]), "r"(b[1]));
}
__device__ __forceinline__ void cp16(uint32_t s, const void* g, int szbytes) {
    asm volatile("cp.async.cg.shared.global [%0], [%1], 16, %2;"
        :: "r"(s), "l"(g), "r"(szbytes));
}
__device__ __forceinline__ void cp_commit() { asm volatile("cp.async.commit_group;" ::: "memory"); }
__device__ __forceinline__ void cp_wait0()  { asm volatile("cp.async.wait_group 0;" ::: "memory"); }
__device__ __forceinline__ void cp_wait1()  { asm volatile("cp.async.wait_group 1;" ::: "memory"); }

// ---------------- fp32 -> fp16 conversion ----------------
__global__ void cvt_kernel(const float* __restrict__ src, __half* __restrict__ dst, int n4) {
    int i = blockIdx.x * 256 + threadIdx.x;
    if (i >= n4) return;
    float4 v = ((const float4*)src)[i];
    ((__half2*)dst)[2 * i]     = __floats2half2_rn(v.x, v.y);
    ((__half2*)dst)[2 * i + 1] = __floats2half2_rn(v.z, v.w);
}

__global__ void cvt2_kernel(const float* __restrict__ s1, __half* __restrict__ d1, int n1,
                            const float* __restrict__ s2, __half* __restrict__ d2, int n2) {
    int i = blockIdx.x * 256 + threadIdx.x;
    const float* s; __half* d; int j;
    if (i < n1) { s = s1; d = d1; j = i; }
    else if (i < n1 + n2) { s = s2; d = d2; j = i - n1; }
    else return;
    float4 v = ((const float4*)s)[j];
    ((__half2*)d)[2 * j]     = __floats2half2_rn(v.x, v.y);
    ((__half2*)d)[2 * j + 1] = __floats2half2_rn(v.z, v.w);
}

// ---------------- HMMA fp16 GEMM, 3-stage cp.async pipeline ----------------
// MODE 0: epilogue gelu(acc+bias) -> Ch fp16
// MODE 1: epilogue acc+bias -> Cf fp32
#define BM_ 128
#define BN_ 128
#define BK_ 64
#define ASTR_ 72
#define BSTR_ 136
#define STG_BYTES 35840
#define GSM_BYTES (3 * STG_BYTES)

template <int MODE>
__global__ void __launch_bounds__(256, 2)
gemm_hmma(const __half* __restrict__ A, const __half* __restrict__ Bm,
          const float* __restrict__ bias,
          float* __restrict__ Cf, __half* __restrict__ Ch,
          int M, int N, int K) {
    extern __shared__ char smraw[];

    int tid = threadIdx.x;
    int wid = tid >> 5, lane = tid & 31;
    int wm = wid & 1, wn = wid >> 1;
    int bn = blockIdx.x * BN_, bm = blockIdx.y * BM_;

    uint32_t uS = smem_u32(smraw);

    float acc[4][4][4];
#pragma unroll
    for (int i = 0; i < 4; i++)
#pragma unroll
        for (int j = 0; j < 4; j++)
#pragma unroll
            for (int q = 0; q < 4; q++) acc[i][j][q] = 0.0f;

    int lo16 = lane & 15, hi16 = lane >> 4;

    auto load_chunk = [&](int kc, int st) {
        uint32_t bA = uS + st * STG_BYTES;
        uint32_t bB = bA + 18432;
#pragma unroll 2
        for (int i = tid; i < 1024; i += 256) {
            int r = i >> 3, u = i & 7;
            int g = (bm + r) * K + kc + u * 8;
            cp16(bA + (uint32_t)(r * ASTR_ + u * 8) * 2, A + g, 16);
        }
#pragma unroll 2
        for (int i = tid; i < 1024; i += 256) {
            int r = i >> 4, u = i & 15;
            int g = (kc + r) * N + bn + u * 8;
            cp16(bB + (uint32_t)(r * BSTR_ + u * 8) * 2, Bm + g, 16);
        }
    };

    int nch = K / BK_;
    load_chunk(0, 0);
    cp_commit();
    load_chunk(BK_, 1);
    cp_commit();

    for (int c = 0; c < nch; c++) {
        int st = c % 3;
        cp_wait1();
        __syncthreads();
        if (c + 2 < nch) load_chunk((c + 2) * BK_, (c + 2) % 3);
        cp_commit();

        uint32_t uA = uS + st * STG_BYTES;
        uint32_t uB = uA + 18432;

#pragma unroll
        for (int ks = 0; ks < 4; ks++) {
            int k0 = ks * 16;
            uint32_t Bf[4][2];
#pragma unroll
            for (int p = 0; p < 2; p++) {
                uint32_t boff = (uint32_t)(((k0 + lo16) * BSTR_ + wn * 32 + p * 16 + 8 * hi16) * 2);
                uint32_t r4[4];
                ldsm_x4_t(r4, uB + boff);
                Bf[p * 2][0] = r4[0]; Bf[p * 2][1] = r4[1];
                Bf[p * 2 + 1][0] = r4[2]; Bf[p * 2 + 1][1] = r4[3];
            }
            uint32_t Af[4][4];
#pragma unroll
            for (int mt = 0; mt < 4; mt++) {
                uint32_t aoff = (uint32_t)(((wm * 64 + mt * 16 + lo16) * ASTR_ + k0 + 8 * hi16) * 2);
                ldsm_x4(Af[mt], uA + aoff);
            }
#pragma unroll
            for (int mt = 0; mt < 4; mt++)
#pragma unroll
                for (int nt = 0; nt < 4; nt++) mma_f16(acc[mt][nt], Af[mt], Bf[nt]);
        }
    }

    int row_in = lane >> 2, colq = (lane & 3) * 2;
#pragma unroll
    for (int mt = 0; mt < 4; mt++) {
#pragma unroll
        for (int nt = 0; nt < 4; nt++) {
            int m0 = bm + wm * 64 + mt * 16 + row_in;
            int n0 = bn + wn * 32 + nt * 8 + colq;
            float b0 = bias[n0], b1 = bias[n0 + 1];
            float v00 = acc[mt][nt][0] + b0, v01 = acc[mt][nt][1] + b1;
            float v10 = acc[mt][nt][2] + b0, v11 = acc[mt][nt][3] + b1;
            if (MODE == 0) {
                *(__half2*)(Ch + m0 * N + n0)       = __floats2half2_rn(gelu_t(v00), gelu_t(v01));
                *(__half2*)(Ch + (m0 + 8) * N + n0) = __floats2half2_rn(gelu_t(v10), gelu_t(v11));
            } else {
                *(float2*)(Cf + m0 * N + n0)       = make_float2(v00, v01);
                *(float2*)(Cf + (m0 + 8) * N + n0) = make_float2(v10, v11);
            }
        }
    }
}

// ---------------- routed experts: fp16 single-pass, 512 threads ----------------
#define RT2_SMEM (44544 * 2)

__global__ void __launch_bounds__(512)
routed_hmma(const __half* __restrict__ Xc,
            const __half* __restrict__ E1c, const float* __restrict__ be1,
            const __half* __restrict__ E2c, const float* __restrict__ be2) {
    extern __shared__ __half sm2[];
    __shared__ int   s_entry[128];
    __shared__ float s_w[128];

    int tid = threadIdx.x, wid = tid >> 5, lane = tid & 31;
    int e = blockIdx.y;
    int base = g_off[e] + blockIdx.x * 128;
    int end  = g_off[e + 1];
    if (base >= end) return;

    __half* sH = sm2 + 17408;

    uint32_t uS  = smem_u32(sm2);
    uint32_t uX  = uS;
    uint32_t uH  = uS + 17408 * 2;
    uint32_t uW1 = uS + 26624 * 2;
    uint32_t uW2 = uS + 35840 * 2;

    for (int i = tid; i < 128; i += 512) {
        int p = base + i;
        if (p < end) {
            int en = g_perm[p];
            s_entry[i] = en;
            s_w[i] = g_top_w[en];
        } else {
            s_entry[i] = -1;
            s_w[i] = 0.0f;
        }
    }
    __syncthreads();

    const __half* W1 = E1c + e * (SD_ * HR_);
    const __half* W2 = E2c + e * (HR_ * SD_);
    const float* b1 = be1 + e * HR_;
    const float* b2 = be2 + e * SD_;

    for (int i = tid; i < 2048; i += 512) {
        int row = i >> 4, u = i & 15;
        int en = s_entry[row];
        int sz = (en >= 0) ? 16 : 0;
        int slot = en >> 1;
        long goff = (en >= 0) ? ((long)(slot >> 3) * DIM_ + (slot & 7) * SD_ + u * 8) : 0;
        cp16(uX + (uint32_t)(row * 136 + u * 8) * 2, Xc + goff, sz);
    }
    for (int i = tid; i < 1024; i += 512) {
        int k = i >> 3, u = i & 7;
        cp16(uW1 + (uint32_t)(k * 72 + u * 8) * 2, W1 + k * HR_ + u * 8, 16);
    }
    cp_commit();
    cp_wait0();
    __syncthreads();

    int wm = wid & 3, wn = wid >> 2;
    int lo16 = lane & 15, hi16 = lane >> 4;
    int row_in = lane >> 2, colq = (lane & 3) * 2;

    float yacc[2][4][4];
#pragma unroll
    for (int i = 0; i < 2; i++)
#pragma unroll
        for (int j = 0; j < 4; j++)
#pragma unroll
            for (int q = 0; q < 4; q++) yacc[i][j][q] = 0.0f;

    for (int ch = 0; ch < 8; ch++) {
        int h0 = ch * 64;

        for (int i = tid; i < 1024; i += 512) {
            int k = i >> 4, u = i & 15;
            cp16(uW2 + (uint32_t)(k * 136 + u * 8) * 2, W2 + (h0 + k) * SD_ + u * 8, 16);
        }
        cp_commit();

        float hacc[2][2][4];
#pragma unroll
        for (int i = 0; i < 2; i++)
#pragma unroll
            for (int j = 0; j < 2; j++)
#pragma unroll
                for (int q = 0; q < 4; q++) hacc[i][j][q] = 0.0f;

#pragma unroll
        for (int ks = 0; ks < 8; ks++) {
            int k0 = ks * 16;
            uint32_t boff = (uint32_t)(((k0 + lo16) * 72 + wn * 16 + 8 * hi16) * 2);
            uint32_t Bf[2][2], r4[4];
            ldsm_x4_t(r4, uW1 + boff);
            Bf[0][0] = r4[0]; Bf[0][1] = r4[1]; Bf[1][0] = r4[2]; Bf[1][1] = r4[3];
            uint32_t Af[2][4];
#pragma unroll
            for (int mt = 0; mt < 2; mt++) {
                uint32_t aoff = (uint32_t)(((wm * 32 + mt * 16 + lo16) * 136 + k0 + 8 * hi16) * 2);
                ldsm_x4(Af[mt], uX + aoff);
            }
#pragma unroll
            for (int mt = 0; mt < 2; mt++)
#pragma unroll
                for (int nt = 0; nt < 2; nt++) mma_f16(hacc[mt][nt], Af[mt], Bf[nt]);
        }

#pragma unroll
        for (int mt = 0; mt < 2; mt++) {
#pragma unroll
            for (int nt = 0; nt < 2; nt++) {
                int n0 = wn * 16 + nt * 8 + colq;
                float bb0 = b1[h0 + n0], bb1 = b1[h0 + n0 + 1];
                int r0 = wm * 32 + mt * 16 + row_in;
                *(__half2*)(sH + r0 * 72 + n0) =
                    __floats2half2_rn(gelu_t(hacc[mt][nt][0] + bb0), gelu_t(hacc[mt][nt][1] + bb1));
                *(__half2*)(sH + (r0 + 8) * 72 + n0) =
                    __floats2half2_rn(gelu_t(hacc[mt][nt][2] + bb0), gelu_t(hacc[mt][nt][3] + bb1));
            }
        }
        cp_wait0();
        __syncthreads();

        if (ch < 7) {
            int h1 = h0 + 64;
            for (int i = tid; i < 1024; i += 512) {
                int k = i >> 3, u = i & 7;
                cp16(uW1 + (uint32_t)(k * 72 + u * 8) * 2, W1 + k * HR_ + h1 + u * 8, 16);
            }
        }
        cp_commit();

#pragma unroll
        for (int ks = 0; ks < 4; ks++) {
            int k0 = ks * 16;
            uint32_t Bf[4][2];
#pragma unroll
            for (int p = 0; p < 2; p++) {
                uint32_t boff = (uint32_t)(((k0 + lo16) * 136 + wn * 32 + p * 16 + 8 * hi16) * 2);
                uint32_t r4[4];
                ldsm_x4_t(r4, uW2 + boff);
                Bf[p * 2][0] = r4[0]; Bf[p * 2][1] = r4[1];
                Bf[p * 2 + 1][0] = r4[2]; Bf[p * 2 + 1][1] = r4[3];
            }
            uint32_t Af[2][4];
#pragma unroll
            for (int mt = 0; mt < 2; mt++) {
                uint32_t aoff = (uint32_t)(((wm * 32 + mt * 16 + lo16) * 72 + k0 + 8 * hi16) * 2);
                ldsm_x4(Af[mt], uH + aoff);
            }
#pragma unroll
            for (int mt = 0; mt < 2; mt++)
#pragma unroll
                for (int nt = 0; nt < 4; nt++) mma_f16(yacc[mt][nt], Af[mt], Bf[nt]);
        }
        cp_wait0();
        __syncthreads();
    }

#pragma unroll
    for (int mt = 0; mt < 2; mt++) {
#pragma unroll
        for (int nt = 0; nt < 4; nt++) {
            int n0 = wn * 32 + nt * 8 + colq;
            float bb0 = b2[n0], bb1 = b2[n0 + 1];
            int r0 = wm * 32 + mt * 16 + row_in;
            int en0 = s_entry[r0];
            if (en0 >= 0) {
                float w = s_w[r0];
                *(float2*)(g_Yent + en0 * SD_ + n0) =
                    make_float2(w * (yacc[mt][nt][0] + bb0), w * (yacc[mt][nt][1] + bb1));
            }
            int en1 = s_entry[r0 + 8];
            if (en1 >= 0) {
                float w = s_w[r0 + 8];
                *(float2*)(g_Yent + en1 * SD_ + n0) =
                    make_float2(w * (yacc[mt][nt][2] + bb0), w * (yacc[mt][nt][3] + bb1));
            }
        }
    }
}

// ---------------- init ----------------
__global__ void init_kernel() {
    int t = threadIdx.x;
    if (t < NE_) { g_cnt[t] = 0; g_wsum[t] = 0.0f; }
}

// ---------------- router ----------------
__global__ void router_kernel(const float* __restrict__ X, const float* __restrict__ Wr) {
    __shared__ float Wrs[SD_ * NE_];
    __shared__ int   scnt[NE_];
    __shared__ float sws[NE_];
    int tid = threadIdx.x;
    for (int i = tid; i < SD_ * NE_; i += 128) Wrs[i] = Wr[i];
    if (tid < NE_) { scnt[tid] = 0; sws[tid] = 0.0f; }
    __syncthreads();

    int slot = blockIdx.x * 128 + tid;
    const float* x = X + (slot >> 3) * DIM_ + (slot & 7) * SD_;
    float lg[NE_];
#pragma unroll
    for (int e = 0; e < NE_; e++) lg[e] = 0.0f;
    for (int k = 0; k < SD_; k++) {
        float xv = x[k];
        const float* wr = &Wrs[k * NE_];
#pragma unroll
        for (int e = 0; e < NE_; e++) lg[e] += xv * wr[e];
    }
    float mx = lg[0];
#pragma unroll
    for (int e = 1; e < NE_; e++) mx = fmaxf(mx, lg[e]);
    float p[NE_]; float sum = 0.0f;
#pragma unroll
    for (int e = 0; e < NE_; e++) { p[e] = expf(lg[e] - mx); sum += p[e]; }
    float inv = 1.0f / sum;
    int i0 = 0; float m0 = -1.0f;
#pragma unroll
    for (int e = 0; e < NE_; e++) if (p[e] > m0) { m0 = p[e]; i0 = e; }
    int i1 = 0; float m1 = -1.0f;
#pragma unroll
    for (int e = 0; e < NE_; e++) if (e != i0 && p[e] > m1) { m1 = p[e]; i1 = e; }
    float w0 = m0 * inv, w1 = m1 * inv;

    g_top_idx[2 * slot]     = i0;
    g_top_idx[2 * slot + 1] = i1;
    g_top_w[2 * slot]       = w0;
    g_top_w[2 * slot + 1]   = w1;

    atomicAdd(&scnt[i0], 1); atomicAdd(&scnt[i1], 1);
    atomicAdd(&sws[i0], w0); atomicAdd(&sws[i1], w1);
    __syncthreads();
    if (tid < NE_) {
        atomicAdd(&g_cnt[tid], scnt[tid]);
        atomicAdd(&g_wsum[tid], sws[tid]);
    }
}

// ---------------- offsets + aux (writes aux straight into out) ----------------
__global__ void offsets_kernel(float* __restrict__ out, int out_size) {
    if (threadIdx.x == 0) {
        int acc = 0; float aux = 0.0f;
        for (int e = 0; e < NE_; e++) {
            g_off[e] = acc; g_cursor[e] = acc;
            acc += g_cnt[e];
            float f = (float)g_cnt[e] / ((float)NS_ * (float)KTOP_);
            float P = g_wsum[e] / (float)NS_;
            aux += f * P;
        }
        g_off[NE_] = acc;
        if (out_size > TOK_ * DIM_) out[TOK_ * DIM_] = (float)NE_ * aux;
    }
}

// ---------------- scatter ----------------
__global__ void scatter_kernel() {
    int slot = blockIdx.x * blockDim.x + threadIdx.x;
    if (slot >= NS_) return;
#pragma unroll
    for (int k = 0; k < KTOP_; k++) {
        int en = 2 * slot + k;
        int e = g_top_idx[en];
        int p = atomicAdd(&g_cursor[e], 1);
        g_perm[p] = en;
    }
}

// ---------------- combine (separate; keeps gemm2 independent of routed) ----------------
__global__ void combine_kernel(float* __restrict__ out) {
    int idx = blockIdx.x * 256 + threadIdx.x;
    int c = idx & (SD_ - 1);
    int slot = idx >> 7;
    int token = slot >> 3, s = slot & 7;
    float add = g_Yent[(2 * slot) * SD_ + c] + g_Yent[(2 * slot + 1) * SD_ + c];
    out[token * DIM_ + s * SD_ + c] += add;
}

// ---------------- launch ----------------
extern "C" void kernel_launch(void* const* d_in, const int* in_sizes, int n_in,
                              void* d_out, int out_size) {
    const float* X   = (const float*)d_in[0];
    const float* Ws1 = (const float*)d_in[1];
    const float* bs1 = (const float*)d_in[2];
    const float* Ws2 = (const float*)d_in[3];
    const float* bs2 = (const float*)d_in[4];
    const float* Wr  = (const float*)d_in[5];
    const float* We1 = (const float*)d_in[6];
    const float* be1 = (const float*)d_in[7];
    const float* We2 = (const float*)d_in[8];
    const float* be2 = (const float*)d_in[9];
    float* out = (float*)d_out;

    static cudaStream_t s2 = nullptr, s3 = nullptr;
    static cudaEvent_t evStart = nullptr, evScatter = nullptr, evX = nullptr;
    static cudaEvent_t evJoin = nullptr, evW2 = nullptr;
    if (s2 == nullptr) {
        cudaStreamCreateWithFlags(&s2, cudaStreamNonBlocking);
        cudaStreamCreateWithFlags(&s3, cudaStreamNonBlocking);
        cudaEventCreateWithFlags(&evStart,   cudaEventDisableTiming);
        cudaEventCreateWithFlags(&evScatter, cudaEventDisableTiming);
        cudaEventCreateWithFlags(&evX,       cudaEventDisableTiming);
        cudaEventCreateWithFlags(&evJoin,    cudaEventDisableTiming);
        cudaEventCreateWithFlags(&evW2,      cudaEventDisableTiming);
    }

    cudaFuncSetAttribute(gemm_hmma<0>, cudaFuncAttributeMaxDynamicSharedMemorySize, GSM_BYTES);
    cudaFuncSetAttribute(gemm_hmma<1>, cudaFuncAttributeMaxDynamicSharedMemorySize, GSM_BYTES);
    cudaFuncSetAttribute(routed_hmma, cudaFuncAttributeMaxDynamicSharedMemorySize, RT2_SMEM);

    __half *Xc, *W1c, *W2c, *H1c, *E1c, *E2c;
    cudaGetSymbolAddress((void**)&Xc,  g_Xc);
    cudaGetSymbolAddress((void**)&W1c, g_W1c);
    cudaGetSymbolAddress((void**)&W2c, g_W2c);
    cudaGetSymbolAddress((void**)&H1c, g_H1c);
    cudaGetSymbolAddress((void**)&E1c, g_E1c);
    cudaGetSymbolAddress((void**)&E2c, g_E2c);

    // ---- fork: three streams ----
    cudaEventRecord(evStart, 0);
    cudaStreamWaitEvent(s2, evStart, 0);
    cudaStreamWaitEvent(s3, evStart, 0);

    // s3: router chain + W2 convert (off the critical path)
    init_kernel<<<1, 64, 0, s3>>>();
    router_kernel<<<NS_ / 128, 128, 0, s3>>>(X, Wr);
    offsets_kernel<<<1, 32, 0, s3>>>(out, out_size);
    scatter_kernel<<<NS_ / 128, 128, 0, s3>>>();
    cudaEventRecord(evScatter, s3);
    cvt_kernel<<<(HSH_ * DIM_ / 4 + 255) / 256, 256, 0, s3>>>(Ws2, W2c, HSH_ * DIM_ / 4);
    cudaEventRecord(evW2, s3);

    // s2: routed prerequisites + routed
    cvt_kernel<<<(TOK_ * DIM_ / 4 + 255) / 256, 256, 0, s2>>>(X, Xc, TOK_ * DIM_ / 4);
    cudaEventRecord(evX, s2);
    cvt2_kernel<<<(NE_ * SD_ * HR_ / 4 + NE_ * HR_ * SD_ / 4 + 255) / 256, 256, 0, s2>>>(
        We1, E1c, NE_ * SD_ * HR_ / 4, We2, E2c, NE_ * HR_ * SD_ / 4);
    cudaStreamWaitEvent(s2, evScatter, 0);
    routed_hmma<<<dim3(NENT_ / 128, NE_), 512, RT2_SMEM, s2>>>(
        Xc, E1c, be1, E2c, be2);
    cudaEventRecord(evJoin, s2);

    // main: shared expert (critical path): cvt W1 -> gemm1 -> gemm2
    cvt_kernel<<<(DIM_ * HSH_ / 4 + 255) / 256, 256>>>(Ws1, W1c, DIM_ * HSH_ / 4);
    cudaStreamWaitEvent(0, evX, 0);
    gemm_hmma<0><<<dim3(HSH_ / BN_, TOK_ / BM_), 256, GSM_BYTES>>>(
        Xc, W1c, bs1, nullptr, H1c, TOK_, HSH_, DIM_);
    cudaStreamWaitEvent(0, evW2, 0);
    gemm_hmma<1><<<dim3(DIM_ / BN_, TOK_ / BM_), 256, GSM_BYTES>>>(
        H1c, W2c, bs2, out, nullptr, TOK_, DIM_, HSH_);

    // ---- join + combine ----
    cudaStreamWaitEvent(0, evJoin, 0);
    combine_kernel<<<(NS_ * SD_) / 256, 256>>>(out);
}

// round 13
// speedup vs baseline: 1.5129x; 1.0730x over previous
#include <cuda_runtime.h>
#include <cuda_fp16.h>
#include <cstdint>

// ---------------- problem constants ----------------
#define B_ 2
#define T_ 2048
#define DIM_ 1024
#define SEG_ 8
#define SD_ 128
#define NE_ 16
#define KTOP_ 2
#define HSH_ 4096
#define HR_ 512
#define TOK_ (B_ * T_)            // 4096 tokens
#define NS_ (TOK_ * SEG_)         // 32768 token-segments
#define NENT_ (NS_ * KTOP_)       // 65536 routed entries

// ---------------- device scratch ----------------
__device__ __half g_Xc[TOK_ * DIM_];
__device__ __half g_W1c[DIM_ * HSH_];
__device__ __half g_W2c[HSH_ * DIM_];
__device__ __half g_H1c[TOK_ * HSH_];
__device__ __half g_E1c[NE_ * SD_ * HR_];
__device__ __half g_E2c[NE_ * HR_ * SD_];
__device__ float g_Yent[NENT_ * SD_];
__device__ int   g_top_idx[NENT_];
__device__ float g_top_w[NENT_];
__device__ int   g_cnt[NE_];
__device__ float g_wsum[NE_];
__device__ int   g_off[NE_ + 1];
__device__ int   g_cursor[NE_];
__device__ int   g_perm[NENT_];
__device__ float g_aux;

__device__ __forceinline__ float gelu_t(float x) {
    float x3 = x * x * x;
    return 0.5f * x * (1.0f + tanhf(0.7978845608028654f * (x + 0.044715f * x3)));
}

__device__ __forceinline__ uint32_t smem_u32(const void* p) {
    uint32_t a;
    asm("{ .reg .u64 t; cvta.to.shared.u64 t, %1; cvt.u32.u64 %0, t; }" : "=r"(a) : "l"(p));
    return a;
}

__device__ __forceinline__ void ldsm_x4(uint32_t r[4], uint32_t addr) {
    asm volatile("ldmatrix.sync.aligned.m8n8.x4.shared.b16 {%0,%1,%2,%3}, [%4];"
        : "=r"(r[0]), "=r"(r[1]), "=r"(r[2]), "=r"(r[3]) : "r"(addr));
}
__device__ __forceinline__ void ldsm_x4_t(uint32_t r[4], uint32_t addr) {
    asm volatile("ldmatrix.sync.aligned.m8n8.x4.trans.shared.b16 {%0,%1,%2,%3}, [%4];"
        : "=r"(r[0]), "=r"(r[1]), "=r"(r[2]), "=r"(r[3]) : "r"(addr));
}
__device__ __forceinline__ void mma_f16(float d[4], const uint32_t a[4], const uint32_t b[2]) {
    asm volatile("mma.sync.aligned.m16n8k16.row.col.f32.f16.f16.f32 "
        "{%0,%1,%2,%3}, {%4,%5,%6,%7}, {%8,%9}, {%0,%1,%2,%3};"
        : "+f"(d[0]), "+f"(d[1]), "+f"(d[2]), "+f"(d[3])
        : "r"(a[0]), "r"(a[1]), "r"(a[2]), "r"(a[3]), "r"(b[0]), "r"(b[1]));
}
__device__ __forceinline__ void cp16(uint32_t s, const void* g, int szbytes) {
    asm volatile("cp.async.cg.shared.global [%0], [%1], 16, %2;"
        :: "r"(s), "l"(g), "r"(szbytes));
}
__device__ __forceinline__ void cp_commit() { asm volatile("cp.async.commit_group;" ::: "memory"); }
__device__ __forceinline__ void cp_wait0()  { asm volatile("cp.async.wait_group 0;" ::: "memory"); }
__device__ __forceinline__ void cp_wait1()  { asm volatile("cp.async.wait_group 1;" ::: "memory"); }

// ---------------- fp32 -> fp16 conversion ----------------
__global__ void cvt_kernel(const float* __restrict__ src, __half* __restrict__ dst, int n4) {
    int i = blockIdx.x * 256 + threadIdx.x;
    if (i >= n4) return;
    float4 v = ((const float4*)src)[i];
    ((__half2*)dst)[2 * i]     = __floats2half2_rn(v.x, v.y);
    ((__half2*)dst)[2 * i + 1] = __floats2half2_rn(v.z, v.w);
}

__global__ void cvt2_kernel(const float* __restrict__ s1, __half* __restrict__ d1, int n1,
                            const float* __restrict__ s2, __half* __restrict__ d2, int n2) {
    int i = blockIdx.x * 256 + threadIdx.x;
    const float* s; __half* d; int j;
    if (i < n1) { s = s1; d = d1; j = i; }
    else if (i < n1 + n2) { s = s2; d = d2; j = i - n1; }
    else return;
    float4 v = ((const float4*)s)[j];
    ((__half2*)d)[2 * j]     = __floats2half2_rn(v.x, v.y);
    ((__half2*)d)[2 * j + 1] = __floats2half2_rn(v.z, v.w);
}

// ---------------- HMMA fp16 GEMM, 3-stage cp.async pipeline, 1 sync/chunk ----------------
#define BM_ 128
#define BN_ 128
#define BK_ 64
#define ASTR_ 72
#define BSTR_ 136
#define STG_BYTES 35840
#define GSM_BYTES (3 * STG_BYTES)

template <int MODE>
__global__ void __launch_bounds__(256, 2)
gemm_hmma(const __half* __restrict__ A, const __half* __restrict__ Bm,
          const float* __restrict__ bias,
          float* __restrict__ Cf, __half* __restrict__ Ch,
          int M, int N, int K) {
    extern __shared__ char smraw[];

    int tid = threadIdx.x;
    int wid = tid >> 5, lane = tid & 31;
    int wm = wid & 1, wn = wid >> 1;
    int bn = blockIdx.x * BN_, bm = blockIdx.y * BM_;

    uint32_t uS = smem_u32(smraw);

    float acc[4][4][4];
#pragma unroll
    for (int i = 0; i < 4; i++)
#pragma unroll
        for (int j = 0; j < 4; j++)
#pragma unroll
            for (int q = 0; q < 4; q++) acc[i][j][q] = 0.0f;

    int lo16 = lane & 15, hi16 = lane >> 4;

    auto load_chunk = [&](int kc, int st) {
        uint32_t bA = uS + st * STG_BYTES;
        uint32_t bB = bA + 18432;
#pragma unroll 2
        for (int i = tid; i < 1024; i += 256) {
            int r = i >> 3, u = i & 7;
            int g = (bm + r) * K + kc + u * 8;
            cp16(bA + (uint32_t)(r * ASTR_ + u * 8) * 2, A + g, 16);
        }
#pragma unroll 2
        for (int i = tid; i < 1024; i += 256) {
            int r = i >> 4, u = i & 15;
            int g = (kc + r) * N + bn + u * 8;
            cp16(bB + (uint32_t)(r * BSTR_ + u * 8) * 2, Bm + g, 16);
        }
    };

    int nch = K / BK_;
    load_chunk(0, 0);
    cp_commit();
    load_chunk(BK_, 1);
    cp_commit();

    for (int c = 0; c < nch; c++) {
        int st = c % 3;
        cp_wait1();
        __syncthreads();
        if (c + 2 < nch) load_chunk((c + 2) * BK_, (c + 2) % 3);
        cp_commit();

        uint32_t uA = uS + st * STG_BYTES;
        uint32_t uB = uA + 18432;

#pragma unroll
        for (int ks = 0; ks < 4; ks++) {
            int k0 = ks * 16;
            uint32_t Bf[4][2];
#pragma unroll
            for (int p = 0; p < 2; p++) {
                uint32_t boff = (uint32_t)(((k0 + lo16) * BSTR_ + wn * 32 + p * 16 + 8 * hi16) * 2);
                uint32_t r4[4];
                ldsm_x4_t(r4, uB + boff);
                Bf[p * 2][0] = r4[0]; Bf[p * 2][1] = r4[1];
                Bf[p * 2 + 1][0] = r4[2]; Bf[p * 2 + 1][1] = r4[3];
            }
            uint32_t Af[4][4];
#pragma unroll
            for (int mt = 0; mt < 4; mt++) {
                uint32_t aoff = (uint32_t)(((wm * 64 + mt * 16 + lo16) * ASTR_ + k0 + 8 * hi16) * 2);
                ldsm_x4(Af[mt], uA + aoff);
            }
#pragma unroll
            for (int mt = 0; mt < 4; mt++)
#pragma unroll
                for (int nt = 0; nt < 4; nt++) mma_f16(acc[mt][nt], Af[mt], Bf[nt]);
        }
    }

    int row_in = lane >> 2, colq = (lane & 3) * 2;
#pragma unroll
    for (int mt = 0; mt < 4; mt++) {
#pragma unroll
        for (int nt = 0; nt < 4; nt++) {
            int m0 = bm + wm * 64 + mt * 16 + row_in;
            int n0 = bn + wn * 32 + nt * 8 + colq;
            float b0 = bias[n0], b1 = bias[n0 + 1];
            float v00 = acc[mt][nt][0] + b0, v01 = acc[mt][nt][1] + b1;
            float v10 = acc[mt][nt][2] + b0, v11 = acc[mt][nt][3] + b1;
            if (MODE == 0) {
                *(__half2*)(Ch + m0 * N + n0)       = __floats2half2_rn(gelu_t(v00), gelu_t(v01));
                *(__half2*)(Ch + (m0 + 8) * N + n0) = __floats2half2_rn(gelu_t(v10), gelu_t(v11));
            } else {
                *(float2*)(Cf + m0 * N + n0)       = make_float2(v00, v01);
                *(float2*)(Cf + (m0 + 8) * N + n0) = make_float2(v10, v11);
            }
        }
    }
}

// ---------------- routed experts: fp16 single-pass, 512 threads ----------------
#define RT2_SMEM (44544 * 2)

__global__ void __launch_bounds__(512)
routed_hmma(const __half* __restrict__ Xc,
            const __half* __restrict__ E1c, const float* __restrict__ be1,
            const __half* __restrict__ E2c, const float* __restrict__ be2) {
    extern __shared__ __half sm2[];
    __shared__ int   s_entry[128];
    __shared__ float s_w[128];

    int tid = threadIdx.x, wid = tid >> 5, lane = tid & 31;
    int e = blockIdx.y;
    int base = g_off[e] + blockIdx.x * 128;
    int end  = g_off[e + 1];
    if (base >= end) return;

    __half* sH = sm2 + 17408;

    uint32_t uS  = smem_u32(sm2);
    uint32_t uX  = uS;
    uint32_t uH  = uS + 17408 * 2;
    uint32_t uW1 = uS + 26624 * 2;
    uint32_t uW2 = uS + 35840 * 2;

    for (int i = tid; i < 128; i += 512) {
        int p = base + i;
        if (p < end) {
            int en = g_perm[p];
            s_entry[i] = en;
            s_w[i] = g_top_w[en];
        } else {
            s_entry[i] = -1;
            s_w[i] = 0.0f;
        }
    }
    __syncthreads();

    const __half* W1 = E1c + e * (SD_ * HR_);
    const __half* W2 = E2c + e * (HR_ * SD_);
    const float* b1 = be1 + e * HR_;
    const float* b2 = be2 + e * SD_;

    for (int i = tid; i < 2048; i += 512) {
        int row = i >> 4, u = i & 15;
        int en = s_entry[row];
        int sz = (en >= 0) ? 16 : 0;
        int slot = en >> 1;
        long goff = (en >= 0) ? ((long)(slot >> 3) * DIM_ + (slot & 7) * SD_ + u * 8) : 0;
        cp16(uX + (uint32_t)(row * 136 + u * 8) * 2, Xc + goff, sz);
    }
    for (int i = tid; i < 1024; i += 512) {
        int k = i >> 3, u = i & 7;
        cp16(uW1 + (uint32_t)(k * 72 + u * 8) * 2, W1 + k * HR_ + u * 8, 16);
    }
    cp_commit();
    cp_wait0();
    __syncthreads();

    int wm = wid & 3, wn = wid >> 2;
    int lo16 = lane & 15, hi16 = lane >> 4;
    int row_in = lane >> 2, colq = (lane & 3) * 2;

    float yacc[2][4][4];
#pragma unroll
    for (int i = 0; i < 2; i++)
#pragma unroll
        for (int j = 0; j < 4; j++)
#pragma unroll
            for (int q = 0; q < 4; q++) yacc[i][j][q] = 0.0f;

    for (int ch = 0; ch < 8; ch++) {
        int h0 = ch * 64;

        for (int i = tid; i < 1024; i += 512) {
            int k = i >> 4, u = i & 15;
            cp16(uW2 + (uint32_t)(k * 136 + u * 8) * 2, W2 + (h0 + k) * SD_ + u * 8, 16);
        }
        cp_commit();

        float hacc[2][2][4];
#pragma unroll
        for (int i = 0; i < 2; i++)
#pragma unroll
            for (int j = 0; j < 2; j++)
#pragma unroll
                for (int q = 0; q < 4; q++) hacc[i][j][q] = 0.0f;

#pragma unroll
        for (int ks = 0; ks < 8; ks++) {
            int k0 = ks * 16;
            uint32_t boff = (uint32_t)(((k0 + lo16) * 72 + wn * 16 + 8 * hi16) * 2);
            uint32_t Bf[2][2], r4[4];
            ldsm_x4_t(r4, uW1 + boff);
            Bf[0][0] = r4[0]; Bf[0][1] = r4[1]; Bf[1][0] = r4[2]; Bf[1][1] = r4[3];
            uint32_t Af[2][4];
#pragma unroll
            for (int mt = 0; mt < 2; mt++) {
                uint32_t aoff = (uint32_t)(((wm * 32 + mt * 16 + lo16) * 136 + k0 + 8 * hi16) * 2);
                ldsm_x4(Af[mt], uX + aoff);
            }
#pragma unroll
            for (int mt = 0; mt < 2; mt++)
#pragma unroll
                for (int nt = 0; nt < 2; nt++) mma_f16(hacc[mt][nt], Af[mt], Bf[nt]);
        }

#pragma unroll
        for (int mt = 0; mt < 2; mt++) {
#pragma unroll
            for (int nt = 0; nt < 2; nt++) {
                int n0 = wn * 16 + nt * 8 + colq;
                float bb0 = b1[h0 + n0], bb1 = b1[h0 + n0 + 1];
                int r0 = wm * 32 + mt * 16 + row_in;
                *(__half2*)(sH + r0 * 72 + n0) =
                    __floats2half2_rn(gelu_t(hacc[mt][nt][0] + bb0), gelu_t(hacc[mt][nt][1] + bb1));
                *(__half2*)(sH + (r0 + 8) * 72 + n0) =
                    __floats2half2_rn(gelu_t(hacc[mt][nt][2] + bb0), gelu_t(hacc[mt][nt][3] + bb1));
            }
        }
        cp_wait0();
        __syncthreads();

        if (ch < 7) {
            int h1 = h0 + 64;
            for (int i = tid; i < 1024; i += 512) {
                int k = i >> 3, u = i & 7;
                cp16(uW1 + (uint32_t)(k * 72 + u * 8) * 2, W1 + k * HR_ + h1 + u * 8, 16);
            }
        }
        cp_commit();

#pragma unroll
        for (int ks = 0; ks < 4; ks++) {
            int k0 = ks * 16;
            uint32_t Bf[4][2];
#pragma unroll
            for (int p = 0; p < 2; p++) {
                uint32_t boff = (uint32_t)(((k0 + lo16) * 136 + wn * 32 + p * 16 + 8 * hi16) * 2);
                uint32_t r4[4];
                ldsm_x4_t(r4, uW2 + boff);
                Bf[p * 2][0] = r4[0]; Bf[p * 2][1] = r4[1];
                Bf[p * 2 + 1][0] = r4[2]; Bf[p * 2 + 1][1] = r4[3];
            }
            uint32_t Af[2][4];
#pragma unroll
            for (int mt = 0; mt < 2; mt++) {
                uint32_t aoff = (uint32_t)(((wm * 32 + mt * 16 + lo16) * 72 + k0 + 8 * hi16) * 2);
                ldsm_x4(Af[mt], uH + aoff);
            }
#pragma unroll
            for (int mt = 0; mt < 2; mt++)
#pragma unroll
                for (int nt = 0; nt < 4; nt++) mma_f16(yacc[mt][nt], Af[mt], Bf[nt]);
        }
        cp_wait0();
        __syncthreads();
    }

#pragma unroll
    for (int mt = 0; mt < 2; mt++) {
#pragma unroll
        for (int nt = 0; nt < 4; nt++) {
            int n0 = wn * 32 + nt * 8 + colq;
            float bb0 = b2[n0], bb1 = b2[n0 + 1];
            int r0 = wm * 32 + mt * 16 + row_in;
            int en0 = s_entry[r0];
            if (en0 >= 0) {
                float w = s_w[r0];
                *(float2*)(g_Yent + en0 * SD_ + n0) =
                    make_float2(w * (yacc[mt][nt][0] + bb0), w * (yacc[mt][nt][1] + bb1));
            }
            int en1 = s_entry[r0 + 8];
            if (en1 >= 0) {
                float w = s_w[r0 + 8];
                *(float2*)(g_Yent + en1 * SD_ + n0) =
                    make_float2(w * (yacc[mt][nt][2] + bb0), w * (yacc[mt][nt][3] + bb1));
            }
        }
    }
}

// ---------------- init ----------------
__global__ void init_kernel() {
    int t = threadIdx.x;
    if (t < NE_) { g_cnt[t] = 0; g_wsum[t] = 0.0f; }
}

// ---------------- router ----------------
__global__ void router_kernel(const float* __restrict__ X, const float* __restrict__ Wr) {
    __shared__ float Wrs[SD_ * NE_];
    __shared__ int   scnt[NE_];
    __shared__ float sws[NE_];
    int tid = threadIdx.x;
    for (int i = tid; i < SD_ * NE_; i += 128) Wrs[i] = Wr[i];
    if (tid < NE_) { scnt[tid] = 0; sws[tid] = 0.0f; }
    __syncthreads();

    int slot = blockIdx.x * 128 + tid;
    const float* x = X + (slot >> 3) * DIM_ + (slot & 7) * SD_;
    float lg[NE_];
#pragma unroll
    for (int e = 0; e < NE_; e++) lg[e] = 0.0f;
    for (int k = 0; k < SD_; k++) {
        float xv = x[k];
        const float* wr = &Wrs[k * NE_];
#pragma unroll
        for (int e = 0; e < NE_; e++) lg[e] += xv * wr[e];
    }
    float mx = lg[0];
#pragma unroll
    for (int e = 1; e < NE_; e++) mx = fmaxf(mx, lg[e]);
    float p[NE_]; float sum = 0.0f;
#pragma unroll
    for (int e = 0; e < NE_; e++) { p[e] = expf(lg[e] - mx); sum += p[e]; }
    float inv = 1.0f / sum;
    int i0 = 0; float m0 = -1.0f;
#pragma unroll
    for (int e = 0; e < NE_; e++) if (p[e] > m0) { m0 = p[e]; i0 = e; }
    int i1 = 0; float m1 = -1.0f;
#pragma unroll
    for (int e = 0; e < NE_; e++) if (e != i0 && p[e] > m1) { m1 = p[e]; i1 = e; }
    float w0 = m0 * inv, w1 = m1 * inv;

    g_top_idx[2 * slot]     = i0;
    g_top_idx[2 * slot + 1] = i1;
    g_top_w[2 * slot]       = w0;
    g_top_w[2 * slot + 1]   = w1;

    atomicAdd(&scnt[i0], 1); atomicAdd(&scnt[i1], 1);
    atomicAdd(&sws[i0], w0); atomicAdd(&sws[i1], w1);
    __syncthreads();
    if (tid < NE_) {
        atomicAdd(&g_cnt[tid], scnt[tid]);
        atomicAdd(&g_wsum[tid], sws[tid]);
    }
}

// ---------------- offsets + aux ----------------
__global__ void offsets_kernel() {
    if (threadIdx.x == 0) {
        int acc = 0; float aux = 0.0f;
        for (int e = 0; e < NE_; e++) {
            g_off[e] = acc; g_cursor[e] = acc;
            acc += g_cnt[e];
            float f = (float)g_cnt[e] / ((float)NS_ * (float)KTOP_);
            float P = g_wsum[e] / (float)NS_;
            aux += f * P;
        }
        g_off[NE_] = acc;
        g_aux = (float)NE_ * aux;
    }
}

// ---------------- scatter ----------------
__global__ void scatter_kernel() {
    int slot = blockIdx.x * blockDim.x + threadIdx.x;
    if (slot >= NS_) return;
#pragma unroll
    for (int k = 0; k < KTOP_; k++) {
        int en = 2 * slot + k;
        int e = g_top_idx[en];
        int p = atomicAdd(&g_cursor[e], 1);
        g_perm[p] = en;
    }
}

// ---------------- combine ----------------
__global__ void combine_kernel(float* __restrict__ out, int out_size) {
    int idx = blockIdx.x * 256 + threadIdx.x;
    int c = idx & (SD_ - 1);
    int slot = idx >> 7;
    int token = slot >> 3, s = slot & 7;
    float add = g_Yent[(2 * slot) * SD_ + c] + g_Yent[(2 * slot + 1) * SD_ + c];
    out[token * DIM_ + s * SD_ + c] += add;
    if (idx == 0 && out_size > TOK_ * DIM_) out[TOK_ * DIM_] = g_aux;
}

// ---------------- launch ----------------
extern "C" void kernel_launch(void* const* d_in, const int* in_sizes, int n_in,
                              void* d_out, int out_size) {
    const float* X   = (const float*)d_in[0];
    const float* Ws1 = (const float*)d_in[1];
    const float* bs1 = (const float*)d_in[2];
    const float* Ws2 = (const float*)d_in[3];
    const float* bs2 = (const float*)d_in[4];
    const float* Wr  = (const float*)d_in[5];
    const float* We1 = (const float*)d_in[6];
    const float* be1 = (const float*)d_in[7];
    const float* We2 = (const float*)d_in[8];
    const float* be2 = (const float*)d_in[9];
    float* out = (float*)d_out;

    static cudaStream_t s2 = nullptr, s3 = nullptr;
    static cudaEvent_t evStart = nullptr, evScatter = nullptr, evX = nullptr, evJoin = nullptr;
    if (s2 == nullptr) {
        cudaStreamCreateWithFlags(&s2, cudaStreamNonBlocking);
        cudaStreamCreateWithFlags(&s3, cudaStreamNonBlocking);
        cudaEventCreateWithFlags(&evStart,   cudaEventDisableTiming);
        cudaEventCreateWithFlags(&evScatter, cudaEventDisableTiming);
        cudaEventCreateWithFlags(&evX,       cudaEventDisableTiming);
        cudaEventCreateWithFlags(&evJoin,    cudaEventDisableTiming);
    }

    cudaFuncSetAttribute(gemm_hmma<0>, cudaFuncAttributeMaxDynamicSharedMemorySize, GSM_BYTES);
    cudaFuncSetAttribute(gemm_hmma<1>, cudaFuncAttributeMaxDynamicSharedMemorySize, GSM_BYTES);
    cudaFuncSetAttribute(routed_hmma, cudaFuncAttributeMaxDynamicSharedMemorySize, RT2_SMEM);

    __half *Xc, *W1c, *W2c, *H1c, *E1c, *E2c;
    cudaGetSymbolAddress((void**)&Xc,  g_Xc);
    cudaGetSymbolAddress((void**)&W1c, g_W1c);
    cudaGetSymbolAddress((void**)&W2c, g_W2c);
    cudaGetSymbolAddress((void**)&H1c, g_H1c);
    cudaGetSymbolAddress((void**)&E1c, g_E1c);
    cudaGetSymbolAddress((void**)&E2c, g_E2c);

    // ---- fork: three streams ----
    cudaEventRecord(evStart, 0);
    cudaStreamWaitEvent(s2, evStart, 0);
    cudaStreamWaitEvent(s3, evStart, 0);

    // s3: router chain (off the critical path)
    init_kernel<<<1, 64, 0, s3>>>();
    router_kernel<<<NS_ / 128, 128, 0, s3>>>(X, Wr);
    offsets_kernel<<<1, 32, 0, s3>>>();
    scatter_kernel<<<NS_ / 128, 128, 0, s3>>>();
    cudaEventRecord(evScatter, s3);

    // s2: routed prerequisites + routed
    cvt_kernel<<<(TOK_ * DIM_ / 4 + 255) / 256, 256, 0, s2>>>(X, Xc, TOK_ * DIM_ / 4);
    cudaEventRecord(evX, s2);
    cvt2_kernel<<<(NE_ * SD_ * HR_ / 4 + NE_ * HR_ * SD_ / 4 + 255) / 256, 256, 0, s2>>>(
        We1, E1c, NE_ * SD_ * HR_ / 4, We2, E2c, NE_ * HR_ * SD_ / 4);
    cudaStreamWaitEvent(s2, evScatter, 0);
    routed_hmma<<<dim3(NENT_ / 128, NE_), 512, RT2_SMEM, s2>>>(
        Xc, E1c, be1, E2c, be2);
    cudaEventRecord(evJoin, s2);

    // main: shared expert (critical path)
    cvt2_kernel<<<(DIM_ * HSH_ / 4 + HSH_ * DIM_ / 4 + 255) / 256, 256>>>(
        Ws1, W1c, DIM_ * HSH_ / 4, Ws2, W2c, HSH_ * DIM_ / 4);
    cudaStreamWaitEvent(0, evX, 0);
    gemm_hmma<0><<<dim3(HSH_ / BN_, TOK_ / BM_), 256, GSM_BYTES>>>(
        Xc, W1c, bs1, nullptr, H1c, TOK_, HSH_, DIM_);
    gemm_hmma<1><<<dim3(DIM_ / BN_, TOK_ / BM_), 256, GSM_BYTES>>>(
        H1c, W2c, bs2, out, nullptr, TOK_, DIM_, HSH_);

    // ---- join + combine ----
    cudaStreamWaitEvent(0, evJoin, 0);
    combine_kernel<<<(NS_ * SD_) / 256, 256>>>(out, out_size);
}

// round 14
// speedup vs baseline: 1.5358x; 1.0151x over previous
#include <cuda_runtime.h>
#include <cuda_fp16.h>
#include <cstdint>

// ---------------- problem constants ----------------
#define B_ 2
#define T_ 2048
#define DIM_ 1024
#define SEG_ 8
#define SD_ 128
#define NE_ 16
#define KTOP_ 2
#define HSH_ 4096
#define HR_ 512
#define TOK_ (B_ * T_)            // 4096 tokens
#define NS_ (TOK_ * SEG_)         // 32768 token-segments
#define NENT_ (NS_ * KTOP_)       // 65536 routed entries

// ---------------- device scratch ----------------
__device__ __half g_Xc[TOK_ * DIM_];
__device__ __half g_W1c[DIM_ * HSH_];
__device__ __half g_W2c[HSH_ * DIM_];
__device__ __half g_H1c[TOK_ * HSH_];
__device__ __half g_E1c[NE_ * SD_ * HR_];
__device__ __half g_E2c[NE_ * HR_ * SD_];
__device__ int   g_top_idx[NENT_];
__device__ float g_top_w[NENT_];
__device__ int   g_cnt[NE_];
__device__ float g_wsum[NE_];
__device__ int   g_off[NE_ + 1];
__device__ int   g_cursor[NE_];
__device__ int   g_perm[NENT_];

__device__ __forceinline__ float gelu_t(float x) {
    float x3 = x * x * x;
    return 0.5f * x * (1.0f + tanhf(0.7978845608028654f * (x + 0.044715f * x3)));
}

__device__ __forceinline__ uint32_t smem_u32(const void* p) {
    uint32_t a;
    asm("{ .reg .u64 t; cvta.to.shared.u64 t, %1; cvt.u32.u64 %0, t; }" : "=r"(a) : "l"(p));
    return a;
}

__device__ __forceinline__ void ldsm_x4(uint32_t r[4], uint32_t addr) {
    asm volatile("ldmatrix.sync.aligned.m8n8.x4.shared.b16 {%0,%1,%2,%3}, [%4];"
        : "=r"(r[0]), "=r"(r[1]), "=r"(r[2]), "=r"(r[3]) : "r"(addr));
}
__device__ __forceinline__ void ldsm_x4_t(uint32_t r[4], uint32_t addr) {
    asm volatile("ldmatrix.sync.aligned.m8n8.x4.trans.shared.b16 {%0,%1,%2,%3}, [%4];"
        : "=r"(r[0]), "=r"(r[1]), "=r"(r[2]), "=r"(r[3]) : "r"(addr));
}
__device__ __forceinline__ void mma_f16(float d[4], const uint32_t a[4], const uint32_t b[2]) {
    asm volatile("mma.sync.aligned.m16n8k16.row.col.f32.f16.f16.f32 "
        "{%0,%1,%2,%3}, {%4,%5,%6,%7}, {%8,%9}, {%0,%1,%2,%3};"
        : "+f"(d[0]), "+f"(d[1]), "+f"(d[2]), "+f"(d[3])
        : "r"(a[0]), "r"(a[1]), "r"(a[2]), "r"(a[3]), "r"(b[0]), "r"(b[1]));
}
__device__ __forceinline__ void cp16(uint32_t s, const void* g, int szbytes) {
    asm volatile("cp.async.cg.shared.global [%0], [%1], 16, %2;"
        :: "r"(s), "l"(g), "r"(szbytes));
}
__device__ __forceinline__ void cp_commit() { asm volatile("cp.async.commit_group;" ::: "memory"); }
__device__ __forceinline__ void cp_wait0()  { asm volatile("cp.async.wait_group 0;" ::: "memory"); }
__device__ __forceinline__ void cp_wait1()  { asm volatile("cp.async.wait_group 1;" ::: "memory"); }
__device__ __forceinline__ void red_add(float* p, float v) {
    asm volatile("red.global.add.f32 [%0], %1;" :: "l"(p), "f"(v) : "memory");
}

// ---------------- zero output ----------------
__global__ void zero_kernel(float* __restrict__ out, int out_size) {
    int i = blockIdx.x * 256 + threadIdx.x;
    int n4 = out_size >> 2;
    if (i < n4) ((float4*)out)[i] = make_float4(0.f, 0.f, 0.f, 0.f);
    if (i == 0)
        for (int j = n4 * 4; j < out_size; j++) out[j] = 0.0f;
}

// ---------------- fp32 -> fp16 conversion ----------------
__global__ void cvt_kernel(const float* __restrict__ src, __half* __restrict__ dst, int n4) {
    int i = blockIdx.x * 256 + threadIdx.x;
    if (i >= n4) return;
    float4 v = ((const float4*)src)[i];
    ((__half2*)dst)[2 * i]     = __floats2half2_rn(v.x, v.y);
    ((__half2*)dst)[2 * i + 1] = __floats2half2_rn(v.z, v.w);
}

__global__ void cvt2_kernel(const float* __restrict__ s1, __half* __restrict__ d1, int n1,
                            const float* __restrict__ s2, __half* __restrict__ d2, int n2) {
    int i = blockIdx.x * 256 + threadIdx.x;
    const float* s; __half* d; int j;
    if (i < n1) { s = s1; d = d1; j = i; }
    else if (i < n1 + n2) { s = s2; d = d2; j = i - n1; }
    else return;
    float4 v = ((const float4*)s)[j];
    ((__half2*)d)[2 * j]     = __floats2half2_rn(v.x, v.y);
    ((__half2*)d)[2 * j + 1] = __floats2half2_rn(v.z, v.w);
}

// ---------------- HMMA fp16 GEMM, 3-stage cp.async pipeline ----------------
// MODE 0: epilogue gelu(acc+bias) -> Ch fp16
// MODE 1: epilogue red.add(acc+bias) into Cf fp32 (atomic-safe vs routed adds)
#define BM_ 128
#define BN_ 128
#define BK_ 64
#define ASTR_ 72
#define BSTR_ 136
#define STG_BYTES 35840
#define GSM_BYTES (3 * STG_BYTES)

template <int MODE>
__global__ void __launch_bounds__(256, 2)
gemm_hmma(const __half* __restrict__ A, const __half* __restrict__ Bm,
          const float* __restrict__ bias,
          float* __restrict__ Cf, __half* __restrict__ Ch,
          int M, int N, int K) {
    extern __shared__ char smraw[];

    int tid = threadIdx.x;
    int wid = tid >> 5, lane = tid & 31;
    int wm = wid & 1, wn = wid >> 1;
    int bn = blockIdx.x * BN_, bm = blockIdx.y * BM_;

    uint32_t uS = smem_u32(smraw);

    float acc[4][4][4];
#pragma unroll
    for (int i = 0; i < 4; i++)
#pragma unroll
        for (int j = 0; j < 4; j++)
#pragma unroll
            for (int q = 0; q < 4; q++) acc[i][j][q] = 0.0f;

    int lo16 = lane & 15, hi16 = lane >> 4;

    auto load_chunk = [&](int kc, int st) {
        uint32_t bA = uS + st * STG_BYTES;
        uint32_t bB = bA + 18432;
#pragma unroll 2
        for (int i = tid; i < 1024; i += 256) {
            int r = i >> 3, u = i & 7;
            int g = (bm + r) * K + kc + u * 8;
            cp16(bA + (uint32_t)(r * ASTR_ + u * 8) * 2, A + g, 16);
        }
#pragma unroll 2
        for (int i = tid; i < 1024; i += 256) {
            int r = i >> 4, u = i & 15;
            int g = (kc + r) * N + bn + u * 8;
            cp16(bB + (uint32_t)(r * BSTR_ + u * 8) * 2, Bm + g, 16);
        }
    };

    int nch = K / BK_;
    load_chunk(0, 0);
    cp_commit();
    load_chunk(BK_, 1);
    cp_commit();

    for (int c = 0; c < nch; c++) {
        int st = c % 3;
        cp_wait1();
        __syncthreads();
        if (c + 2 < nch) load_chunk((c + 2) * BK_, (c + 2) % 3);
        cp_commit();

        uint32_t uA = uS + st * STG_BYTES;
        uint32_t uB = uA + 18432;

#pragma unroll
        for (int ks = 0; ks < 4; ks++) {
            int k0 = ks * 16;
            uint32_t Bf[4][2];
#pragma unroll
            for (int p = 0; p < 2; p++) {
                uint32_t boff = (uint32_t)(((k0 + lo16) * BSTR_ + wn * 32 + p * 16 + 8 * hi16) * 2);
                uint32_t r4[4];
                ldsm_x4_t(r4, uB + boff);
                Bf[p * 2][0] = r4[0]; Bf[p * 2][1] = r4[1];
                Bf[p * 2 + 1][0] = r4[2]; Bf[p * 2 + 1][1] = r4[3];
            }
            uint32_t Af[4][4];
#pragma unroll
            for (int mt = 0; mt < 4; mt++) {
                uint32_t aoff = (uint32_t)(((wm * 64 + mt * 16 + lo16) * ASTR_ + k0 + 8 * hi16) * 2);
                ldsm_x4(Af[mt], uA + aoff);
            }
#pragma unroll
            for (int mt = 0; mt < 4; mt++)
#pragma unroll
                for (int nt = 0; nt < 4; nt++) mma_f16(acc[mt][nt], Af[mt], Bf[nt]);
        }
    }

    int row_in = lane >> 2, colq = (lane & 3) * 2;
#pragma unroll
    for (int mt = 0; mt < 4; mt++) {
#pragma unroll
        for (int nt = 0; nt < 4; nt++) {
            int m0 = bm + wm * 64 + mt * 16 + row_in;
            int n0 = bn + wn * 32 + nt * 8 + colq;
            float b0 = bias[n0], b1 = bias[n0 + 1];
            float v00 = acc[mt][nt][0] + b0, v01 = acc[mt][nt][1] + b1;
            float v10 = acc[mt][nt][2] + b0, v11 = acc[mt][nt][3] + b1;
            if (MODE == 0) {
                *(__half2*)(Ch + m0 * N + n0)       = __floats2half2_rn(gelu_t(v00), gelu_t(v01));
                *(__half2*)(Ch + (m0 + 8) * N + n0) = __floats2half2_rn(gelu_t(v10), gelu_t(v11));
            } else {
                red_add(Cf + m0 * N + n0, v00);
                red_add(Cf + m0 * N + n0 + 1, v01);
                red_add(Cf + (m0 + 8) * N + n0, v10);
                red_add(Cf + (m0 + 8) * N + n0 + 1, v11);
            }
        }
    }
}

// ---------------- routed experts: fp16 single-pass, 512 threads ----------------
#define RT2_SMEM (44544 * 2)

__global__ void __launch_bounds__(512)
routed_hmma(const __half* __restrict__ Xc,
            const __half* __restrict__ E1c, const float* __restrict__ be1,
            const __half* __restrict__ E2c, const float* __restrict__ be2,
            float* __restrict__ out) {
    extern __shared__ __half sm2[];
    __shared__ int   s_entry[128];
    __shared__ float s_w[128];

    int tid = threadIdx.x, wid = tid >> 5, lane = tid & 31;
    int e = blockIdx.y;
    int base = g_off[e] + blockIdx.x * 128;
    int end  = g_off[e + 1];
    if (base >= end) return;

    __half* sH = sm2 + 17408;

    uint32_t uS  = smem_u32(sm2);
    uint32_t uX  = uS;
    uint32_t uH  = uS + 17408 * 2;
    uint32_t uW1 = uS + 26624 * 2;
    uint32_t uW2 = uS + 35840 * 2;

    for (int i = tid; i < 128; i += 512) {
        int p = base + i;
        if (p < end) {
            int en = g_perm[p];
            s_entry[i] = en;
            s_w[i] = g_top_w[en];
        } else {
            s_entry[i] = -1;
            s_w[i] = 0.0f;
        }
    }
    __syncthreads();

    const __half* W1 = E1c + e * (SD_ * HR_);
    const __half* W2 = E2c + e * (HR_ * SD_);
    const float* b1 = be1 + e * HR_;
    const float* b2 = be2 + e * SD_;

    for (int i = tid; i < 2048; i += 512) {
        int row = i >> 4, u = i & 15;
        int en = s_entry[row];
        int sz = (en >= 0) ? 16 : 0;
        int slot = en >> 1;
        long goff = (en >= 0) ? ((long)(slot >> 3) * DIM_ + (slot & 7) * SD_ + u * 8) : 0;
        cp16(uX + (uint32_t)(row * 136 + u * 8) * 2, Xc + goff, sz);
    }
    for (int i = tid; i < 1024; i += 512) {
        int k = i >> 3, u = i & 7;
        cp16(uW1 + (uint32_t)(k * 72 + u * 8) * 2, W1 + k * HR_ + u * 8, 16);
    }
    cp_commit();
    cp_wait0();
    __syncthreads();

    int wm = wid & 3, wn = wid >> 2;
    int lo16 = lane & 15, hi16 = lane >> 4;
    int row_in = lane >> 2, colq = (lane & 3) * 2;

    float yacc[2][4][4];
#pragma unroll
    for (int i = 0; i < 2; i++)
#pragma unroll
        for (int j = 0; j < 4; j++)
#pragma unroll
            for (int q = 0; q < 4; q++) yacc[i][j][q] = 0.0f;

    for (int ch = 0; ch < 8; ch++) {
        int h0 = ch * 64;

        for (int i = tid; i < 1024; i += 512) {
            int k = i >> 4, u = i & 15;
            cp16(uW2 + (uint32_t)(k * 136 + u * 8) * 2, W2 + (h0 + k) * SD_ + u * 8, 16);
        }
        cp_commit();

        float hacc[2][2][4];
#pragma unroll
        for (int i = 0; i < 2; i++)
#pragma unroll
            for (int j = 0; j < 2; j++)
#pragma unroll
                for (int q = 0; q < 4; q++) hacc[i][j][q] = 0.0f;

#pragma unroll
        for (int ks = 0; ks < 8; ks++) {
            int k0 = ks * 16;
            uint32_t boff = (uint32_t)(((k0 + lo16) * 72 + wn * 16 + 8 * hi16) * 2);
            uint32_t Bf[2][2], r4[4];
            ldsm_x4_t(r4, uW1 + boff);
            Bf[0][0] = r4[0]; Bf[0][1] = r4[1]; Bf[1][0] = r4[2]; Bf[1][1] = r4[3];
            uint32_t Af[2][4];
#pragma unroll
            for (int mt = 0; mt < 2; mt++) {
                uint32_t aoff = (uint32_t)(((wm * 32 + mt * 16 + lo16) * 136 + k0 + 8 * hi16) * 2);
                ldsm_x4(Af[mt], uX + aoff);
            }
#pragma unroll
            for (int mt = 0; mt < 2; mt++)
#pragma unroll
                for (int nt = 0; nt < 2; nt++) mma_f16(hacc[mt][nt], Af[mt], Bf[nt]);
        }

#pragma unroll
        for (int mt = 0; mt < 2; mt++) {
#pragma unroll
            for (int nt = 0; nt < 2; nt++) {
                int n0 = wn * 16 + nt * 8 + colq;
                float bb0 = b1[h0 + n0], bb1 = b1[h0 + n0 + 1];
                int r0 = wm * 32 + mt * 16 + row_in;
                *(__half2*)(sH + r0 * 72 + n0) =
                    __floats2half2_rn(gelu_t(hacc[mt][nt][0] + bb0), gelu_t(hacc[mt][nt][1] + bb1));
                *(__half2*)(sH + (r0 + 8) * 72 + n0) =
                    __floats2half2_rn(gelu_t(hacc[mt][nt][2] + bb0), gelu_t(hacc[mt][nt][3] + bb1));
            }
        }
        cp_wait0();
        __syncthreads();

        if (ch < 7) {
            int h1 = h0 + 64;
            for (int i = tid; i < 1024; i += 512) {
                int k = i >> 3, u = i & 7;
                cp16(uW1 + (uint32_t)(k * 72 + u * 8) * 2, W1 + k * HR_ + h1 + u * 8, 16);
            }
        }
        cp_commit();

#pragma unroll
        for (int ks = 0; ks < 4; ks++) {
            int k0 = ks * 16;
            uint32_t Bf[4][2];
#pragma unroll
            for (int p = 0; p < 2; p++) {
                uint32_t boff = (uint32_t)(((k0 + lo16) * 136 + wn * 32 + p * 16 + 8 * hi16) * 2);
                uint32_t r4[4];
                ldsm_x4_t(r4, uW2 + boff);
                Bf[p * 2][0] = r4[0]; Bf[p * 2][1] = r4[1];
                Bf[p * 2 + 1][0] = r4[2]; Bf[p * 2 + 1][1] = r4[3];
            }
            uint32_t Af[2][4];
#pragma unroll
            for (int mt = 0; mt < 2; mt++) {
                uint32_t aoff = (uint32_t)(((wm * 32 + mt * 16 + lo16) * 72 + k0 + 8 * hi16) * 2);
                ldsm_x4(Af[mt], uH + aoff);
            }
#pragma unroll
            for (int mt = 0; mt < 2; mt++)
#pragma unroll
                for (int nt = 0; nt < 4; nt++) mma_f16(yacc[mt][nt], Af[mt], Bf[nt]);
        }
        cp_wait0();
        __syncthreads();
    }

    // epilogue: red.add w*(y+b2) directly into out[token*DIM + s*SD + c]
#pragma unroll
    for (int mt = 0; mt < 2; mt++) {
#pragma unroll
        for (int nt = 0; nt < 4; nt++) {
            int n0 = wn * 32 + nt * 8 + colq;
            float bb0 = b2[n0], bb1 = b2[n0 + 1];
            int r0 = wm * 32 + mt * 16 + row_in;
            int en0 = s_entry[r0];
            if (en0 >= 0) {
                float w = s_w[r0];
                int slot = en0 >> 1;
                float* dst = out + (slot >> 3) * DIM_ + (slot & 7) * SD_ + n0;
                red_add(dst, w * (yacc[mt][nt][0] + bb0));
                red_add(dst + 1, w * (yacc[mt][nt][1] + bb1));
            }
            int en1 = s_entry[r0 + 8];
            if (en1 >= 0) {
                float w = s_w[r0 + 8];
                int slot = en1 >> 1;
                float* dst = out + (slot >> 3) * DIM_ + (slot & 7) * SD_ + n0;
                red_add(dst, w * (yacc[mt][nt][2] + bb0));
                red_add(dst + 1, w * (yacc[mt][nt][3] + bb1));
            }
        }
    }
}

// ---------------- init ----------------
__global__ void init_kernel() {
    int t = threadIdx.x;
    if (t < NE_) { g_cnt[t] = 0; g_wsum[t] = 0.0f; }
}

// ---------------- router ----------------
__global__ void router_kernel(const float* __restrict__ X, const float* __restrict__ Wr) {
    __shared__ float Wrs[SD_ * NE_];
    __shared__ int   scnt[NE_];
    __shared__ float sws[NE_];
    int tid = threadIdx.x;
    for (int i = tid; i < SD_ * NE_; i += 128) Wrs[i] = Wr[i];
    if (tid < NE_) { scnt[tid] = 0; sws[tid] = 0.0f; }
    __syncthreads();

    int slot = blockIdx.x * 128 + tid;
    const float* x = X + (slot >> 3) * DIM_ + (slot & 7) * SD_;
    float lg[NE_];
#pragma unroll
    for (int e = 0; e < NE_; e++) lg[e] = 0.0f;
    for (int k = 0; k < SD_; k++) {
        float xv = x[k];
        const float* wr = &Wrs[k * NE_];
#pragma unroll
        for (int e = 0; e < NE_; e++) lg[e] += xv * wr[e];
    }
    float mx = lg[0];
#pragma unroll
    for (int e = 1; e < NE_; e++) mx = fmaxf(mx, lg[e]);
    float p[NE_]; float sum = 0.0f;
#pragma unroll
    for (int e = 0; e < NE_; e++) { p[e] = expf(lg[e] - mx); sum += p[e]; }
    float inv = 1.0f / sum;
    int i0 = 0; float m0 = -1.0f;
#pragma unroll
    for (int e = 0; e < NE_; e++) if (p[e] > m0) { m0 = p[e]; i0 = e; }
    int i1 = 0; float m1 = -1.0f;
#pragma unroll
    for (int e = 0; e < NE_; e++) if (e != i0 && p[e] > m1) { m1 = p[e]; i1 = e; }
    float w0 = m0 * inv, w1 = m1 * inv;

    g_top_idx[2 * slot]     = i0;
    g_top_idx[2 * slot + 1] = i1;
    g_top_w[2 * slot]       = w0;
    g_top_w[2 * slot + 1]   = w1;

    atomicAdd(&scnt[i0], 1); atomicAdd(&scnt[i1], 1);
    atomicAdd(&sws[i0], w0); atomicAdd(&sws[i1], w1);
    __syncthreads();
    if (tid < NE_) {
        atomicAdd(&g_cnt[tid], scnt[tid]);
        atomicAdd(&g_wsum[tid], sws[tid]);
    }
}

// ---------------- offsets + aux (writes aux into zeroed out) ----------------
__global__ void offsets_kernel(float* __restrict__ out, int out_size) {
    if (threadIdx.x == 0) {
        int acc = 0; float aux = 0.0f;
        for (int e = 0; e < NE_; e++) {
            g_off[e] = acc; g_cursor[e] = acc;
            acc += g_cnt[e];
            float f = (float)g_cnt[e] / ((float)NS_ * (float)KTOP_);
            float P = g_wsum[e] / (float)NS_;
            aux += f * P;
        }
        g_off[NE_] = acc;
        if (out_size > TOK_ * DIM_) out[TOK_ * DIM_] = (float)NE_ * aux;
    }
}

// ---------------- scatter ----------------
__global__ void scatter_kernel() {
    int slot = blockIdx.x * blockDim.x + threadIdx.x;
    if (slot >= NS_) return;
#pragma unroll
    for (int k = 0; k < KTOP_; k++) {
        int en = 2 * slot + k;
        int e = g_top_idx[en];
        int p = atomicAdd(&g_cursor[e], 1);
        g_perm[p] = en;
    }
}

// ---------------- launch ----------------
extern "C" void kernel_launch(void* const* d_in, const int* in_sizes, int n_in,
                              void* d_out, int out_size) {
    const float* X   = (const float*)d_in[0];
    const float* Ws1 = (const float*)d_in[1];
    const float* bs1 = (const float*)d_in[2];
    const float* Ws2 = (const float*)d_in[3];
    const float* bs2 = (const float*)d_in[4];
    const float* Wr  = (const float*)d_in[5];
    const float* We1 = (const float*)d_in[6];
    const float* be1 = (const float*)d_in[7];
    const float* We2 = (const float*)d_in[8];
    const float* be2 = (const float*)d_in[9];
    float* out = (float*)d_out;

    static cudaStream_t s2 = nullptr, s3 = nullptr;
    static cudaEvent_t evStart = nullptr, evScatter = nullptr, evX = nullptr;
    static cudaEvent_t evJoin = nullptr, evZero = nullptr;
    if (s2 == nullptr) {
        cudaStreamCreateWithFlags(&s2, cudaStreamNonBlocking);
        cudaStreamCreateWithFlags(&s3, cudaStreamNonBlocking);
        cudaEventCreateWithFlags(&evStart,   cudaEventDisableTiming);
        cudaEventCreateWithFlags(&evScatter, cudaEventDisableTiming);
        cudaEventCreateWithFlags(&evX,       cudaEventDisableTiming);
        cudaEventCreateWithFlags(&evJoin,    cudaEventDisableTiming);
        cudaEventCreateWithFlags(&evZero,    cudaEventDisableTiming);
    }

    cudaFuncSetAttribute(gemm_hmma<0>, cudaFuncAttributeMaxDynamicSharedMemorySize, GSM_BYTES);
    cudaFuncSetAttribute(gemm_hmma<1>, cudaFuncAttributeMaxDynamicSharedMemorySize, GSM_BYTES);
    cudaFuncSetAttribute(routed_hmma, cudaFuncAttributeMaxDynamicSharedMemorySize, RT2_SMEM);

    __half *Xc, *W1c, *W2c, *H1c, *E1c, *E2c;
    cudaGetSymbolAddress((void**)&Xc,  g_Xc);
    cudaGetSymbolAddress((void**)&W1c, g_W1c);
    cudaGetSymbolAddress((void**)&W2c, g_W2c);
    cudaGetSymbolAddress((void**)&H1c, g_H1c);
    cudaGetSymbolAddress((void**)&E1c, g_E1c);
    cudaGetSymbolAddress((void**)&E2c, g_E2c);

    // ---- main: zero the output first (both gemm2 and routed red.add into it) ----
    zero_kernel<<<(out_size / 4 + 255) / 256, 256>>>(out, out_size);
    cudaEventRecord(evZero, 0);

    // ---- fork: three streams ----
    cudaEventRecord(evStart, 0);
    cudaStreamWaitEvent(s2, evStart, 0);
    cudaStreamWaitEvent(s3, evZero, 0);   // s3 writes aux into out -> after zero

    // s3: router chain (off the critical path)
    init_kernel<<<1, 64, 0, s3>>>();
    router_kernel<<<NS_ / 128, 128, 0, s3>>>(X, Wr);
    offsets_kernel<<<1, 32, 0, s3>>>(out, out_size);
    scatter_kernel<<<NS_ / 128, 128, 0, s3>>>();
    cudaEventRecord(evScatter, s3);

    // s2: routed prerequisites + routed (scatter wait transitively covers evZero)
    cvt_kernel<<<(TOK_ * DIM_ / 4 + 255) / 256, 256, 0, s2>>>(X, Xc, TOK_ * DIM_ / 4);
    cudaEventRecord(evX, s2);
    cvt2_kernel<<<(NE_ * SD_ * HR_ / 4 + NE_ * HR_ * SD_ / 4 + 255) / 256, 256, 0, s2>>>(
        We1, E1c, NE_ * SD_ * HR_ / 4, We2, E2c, NE_ * HR_ * SD_ / 4);
    cudaStreamWaitEvent(s2, evScatter, 0);
    routed_hmma<<<dim3(NENT_ / 128, NE_), 512, RT2_SMEM, s2>>>(
        Xc, E1c, be1, E2c, be2, out);
    cudaEventRecord(evJoin, s2);

    // main: shared expert (critical path); gemm2 red.adds into zeroed out
    cvt2_kernel<<<(DIM_ * HSH_ / 4 + HSH_ * DIM_ / 4 + 255) / 256, 256>>>(
        Ws1, W1c, DIM_ * HSH_ / 4, Ws2, W2c, HSH_ * DIM_ / 4);
    cudaStreamWaitEvent(0, evX, 0);
    gemm_hmma<0><<<dim3(HSH_ / BN_, TOK_ / BM_), 256, GSM_BYTES>>>(
        Xc, W1c, bs1, nullptr, H1c, TOK_, HSH_, DIM_);
    gemm_hmma<1><<<dim3(DIM_ / BN_, TOK_ / BM_), 256, GSM_BYTES>>>(
        H1c, W2c, bs2, out, nullptr, TOK_, DIM_, HSH_);

    // ---- join: graph completes when routed's reductions are done too ----
    cudaStreamWaitEvent(0, evJoin, 0);
}

// round 15
// speedup vs baseline: 1.6257x; 1.0585x over previous
#include <cuda_runtime.h>
#include <cuda_fp16.h>
#include <cstdint>

// ---------------- problem constants ----------------
#define B_ 2
#define T_ 2048
#define DIM_ 1024
#define SEG_ 8
#define SD_ 128
#define NE_ 16
#define KTOP_ 2
#define HSH_ 4096
#define HR_ 512
#define TOK_ (B_ * T_)            // 4096 tokens
#define NS_ (TOK_ * SEG_)         // 32768 token-segments
#define NENT_ (NS_ * KTOP_)       // 65536 routed entries

// ---------------- device scratch ----------------
__device__ __half g_Xc[TOK_ * DIM_];
__device__ __half g_W1c[DIM_ * HSH_];
__device__ __half g_W2c[HSH_ * DIM_];
__device__ __half g_H1c[TOK_ * HSH_];
__device__ __half g_E1c[NE_ * SD_ * HR_];
__device__ __half g_E2c[NE_ * HR_ * SD_];
__device__ int   g_top_idx[NENT_];
__device__ float g_top_w[NENT_];
__device__ int   g_cnt[NE_];
__device__ float g_wsum[NE_];
__device__ int   g_off[NE_ + 1];
__device__ int   g_cursor[NE_];
__device__ int   g_perm[NENT_];

__device__ __forceinline__ float gelu_t(float x) {
    float x3 = x * x * x;
    return 0.5f * x * (1.0f + tanhf(0.7978845608028654f * (x + 0.044715f * x3)));
}

__device__ __forceinline__ uint32_t smem_u32(const void* p) {
    uint32_t a;
    asm("{ .reg .u64 t; cvta.to.shared.u64 t, %1; cvt.u32.u64 %0, t; }" : "=r"(a) : "l"(p));
    return a;
}

__device__ __forceinline__ void ldsm_x4(uint32_t r[4], uint32_t addr) {
    asm volatile("ldmatrix.sync.aligned.m8n8.x4.shared.b16 {%0,%1,%2,%3}, [%4];"
        : "=r"(r[0]), "=r"(r[1]), "=r"(r[2]), "=r"(r[3]) : "r"(addr));
}
__device__ __forceinline__ void ldsm_x4_t(uint32_t r[4], uint32_t addr) {
    asm volatile("ldmatrix.sync.aligned.m8n8.x4.trans.shared.b16 {%0,%1,%2,%3}, [%4];"
        : "=r"(r[0]), "=r"(r[1]), "=r"(r[2]), "=r"(r[3]) : "r"(addr));
}
__device__ __forceinline__ void mma_f16(float d[4], const uint32_t a[4], const uint32_t b[2]) {
    asm volatile("mma.sync.aligned.m16n8k16.row.col.f32.f16.f16.f32 "
        "{%0,%1,%2,%3}, {%4,%5,%6,%7}, {%8,%9}, {%0,%1,%2,%3};"
        : "+f"(d[0]), "+f"(d[1]), "+f"(d[2]), "+f"(d[3])
        : "r"(a[0]), "r"(a[1]), "r"(a[2]), "r"(a[3]), "r"(b[0]), "r"(b[1]));
}
__device__ __forceinline__ void cp16(uint32_t s, const void* g, int szbytes) {
    asm volatile("cp.async.cg.shared.global [%0], [%1], 16, %2;"
        :: "r"(s), "l"(g), "r"(szbytes));
}
__device__ __forceinline__ void cp_commit() { asm volatile("cp.async.commit_group;" ::: "memory"); }
__device__ __forceinline__ void cp_wait0()  { asm volatile("cp.async.wait_group 0;" ::: "memory"); }
__device__ __forceinline__ void cp_wait1()  { asm volatile("cp.async.wait_group 1;" ::: "memory"); }
__device__ __forceinline__ void red_add(float* p, float v) {
    asm volatile("red.global.add.f32 [%0], %1;" :: "l"(p), "f"(v) : "memory");
}

// ---------------- zero output ----------------
__global__ void zero_kernel(float* __restrict__ out, int out_size) {
    int i = blockIdx.x * 256 + threadIdx.x;
    int n4 = out_size >> 2;
    if (i < n4) ((float4*)out)[i] = make_float4(0.f, 0.f, 0.f, 0.f);
    if (i == 0)
        for (int j = n4 * 4; j < out_size; j++) out[j] = 0.0f;
}

// ---------------- fp32 -> fp16 conversion ----------------
__global__ void cvt_kernel(const float* __restrict__ src, __half* __restrict__ dst, int n4) {
    int i = blockIdx.x * 256 + threadIdx.x;
    if (i >= n4) return;
    float4 v = ((const float4*)src)[i];
    ((__half2*)dst)[2 * i]     = __floats2half2_rn(v.x, v.y);
    ((__half2*)dst)[2 * i + 1] = __floats2half2_rn(v.z, v.w);
}

__global__ void cvt2_kernel(const float* __restrict__ s1, __half* __restrict__ d1, int n1,
                            const float* __restrict__ s2, __half* __restrict__ d2, int n2) {
    int i = blockIdx.x * 256 + threadIdx.x;
    const float* s; __half* d; int j;
    if (i < n1) { s = s1; d = d1; j = i; }
    else if (i < n1 + n2) { s = s2; d = d2; j = i - n1; }
    else return;
    float4 v = ((const float4*)s)[j];
    ((__half2*)d)[2 * j]     = __floats2half2_rn(v.x, v.y);
    ((__half2*)d)[2 * j + 1] = __floats2half2_rn(v.z, v.w);
}

// ---------------- HMMA fp16 GEMM, 3-stage cp.async pipeline ----------------
// MODE 0: epilogue gelu(acc+bias) -> Ch fp16
// MODE 1: epilogue red.add(acc+bias) into Cf fp32
#define BM_ 128
#define BN_ 128
#define BK_ 64
#define ASTR_ 72
#define BSTR_ 136
#define STG_BYTES 35840
#define GSM_BYTES (3 * STG_BYTES)

template <int MODE>
__global__ void __launch_bounds__(256, 2)
gemm_hmma(const __half* __restrict__ A, const __half* __restrict__ Bm,
          const float* __restrict__ bias,
          float* __restrict__ Cf, __half* __restrict__ Ch,
          int M, int N, int K) {
    extern __shared__ char smraw[];

    int tid = threadIdx.x;
    int wid = tid >> 5, lane = tid & 31;
    int wm = wid & 1, wn = wid >> 1;
    int bn = blockIdx.x * BN_, bm = blockIdx.y * BM_;

    uint32_t uS = smem_u32(smraw);

    float acc[4][4][4];
#pragma unroll
    for (int i = 0; i < 4; i++)
#pragma unroll
        for (int j = 0; j < 4; j++)
#pragma unroll
            for (int q = 0; q < 4; q++) acc[i][j][q] = 0.0f;

    int lo16 = lane & 15, hi16 = lane >> 4;

    auto load_chunk = [&](int kc, int st) {
        uint32_t bA = uS + st * STG_BYTES;
        uint32_t bB = bA + 18432;
#pragma unroll 2
        for (int i = tid; i < 1024; i += 256) {
            int r = i >> 3, u = i & 7;
            int g = (bm + r) * K + kc + u * 8;
            cp16(bA + (uint32_t)(r * ASTR_ + u * 8) * 2, A + g, 16);
        }
#pragma unroll 2
        for (int i = tid; i < 1024; i += 256) {
            int r = i >> 4, u = i & 15;
            int g = (kc + r) * N + bn + u * 8;
            cp16(bB + (uint32_t)(r * BSTR_ + u * 8) * 2, Bm + g, 16);
        }
    };

    int nch = K / BK_;
    load_chunk(0, 0);
    cp_commit();
    load_chunk(BK_, 1);
    cp_commit();

    for (int c = 0; c < nch; c++) {
        int st = c % 3;
        cp_wait1();
        __syncthreads();
        if (c + 2 < nch) load_chunk((c + 2) * BK_, (c + 2) % 3);
        cp_commit();

        uint32_t uA = uS + st * STG_BYTES;
        uint32_t uB = uA + 18432;

#pragma unroll
        for (int ks = 0; ks < 4; ks++) {
            int k0 = ks * 16;
            uint32_t Bf[4][2];
#pragma unroll
            for (int p = 0; p < 2; p++) {
                uint32_t boff = (uint32_t)(((k0 + lo16) * BSTR_ + wn * 32 + p * 16 + 8 * hi16) * 2);
                uint32_t r4[4];
                ldsm_x4_t(r4, uB + boff);
                Bf[p * 2][0] = r4[0]; Bf[p * 2][1] = r4[1];
                Bf[p * 2 + 1][0] = r4[2]; Bf[p * 2 + 1][1] = r4[3];
            }
            uint32_t Af[4][4];
#pragma unroll
            for (int mt = 0; mt < 4; mt++) {
                uint32_t aoff = (uint32_t)(((wm * 64 + mt * 16 + lo16) * ASTR_ + k0 + 8 * hi16) * 2);
                ldsm_x4(Af[mt], uA + aoff);
            }
#pragma unroll
            for (int mt = 0; mt < 4; mt++)
#pragma unroll
                for (int nt = 0; nt < 4; nt++) mma_f16(acc[mt][nt], Af[mt], Bf[nt]);
        }
    }

    int row_in = lane >> 2, colq = (lane & 3) * 2;
#pragma unroll
    for (int mt = 0; mt < 4; mt++) {
#pragma unroll
        for (int nt = 0; nt < 4; nt++) {
            int m0 = bm + wm * 64 + mt * 16 + row_in;
            int n0 = bn + wn * 32 + nt * 8 + colq;
            float b0 = bias[n0], b1 = bias[n0 + 1];
            float v00 = acc[mt][nt][0] + b0, v01 = acc[mt][nt][1] + b1;
            float v10 = acc[mt][nt][2] + b0, v11 = acc[mt][nt][3] + b1;
            if (MODE == 0) {
                *(__half2*)(Ch + m0 * N + n0)       = __floats2half2_rn(gelu_t(v00), gelu_t(v01));
                *(__half2*)(Ch + (m0 + 8) * N + n0) = __floats2half2_rn(gelu_t(v10), gelu_t(v11));
            } else {
                red_add(Cf + m0 * N + n0, v00);
                red_add(Cf + m0 * N + n0 + 1, v01);
                red_add(Cf + (m0 + 8) * N + n0, v10);
                red_add(Cf + (m0 + 8) * N + n0 + 1, v11);
            }
        }
    }
}

// ---------------- routed experts: fp16, 512 threads, hidden chunks of 128 ----------------
// smem (half elems, stride 136): sX @0, sH @17408, W1 @34816, W2 @52224
#define RT2_SMEM (4 * 17408 * 2)

__global__ void __launch_bounds__(512)
routed_hmma(const __half* __restrict__ Xc,
            const __half* __restrict__ E1c, const float* __restrict__ be1,
            const __half* __restrict__ E2c, const float* __restrict__ be2,
            float* __restrict__ out) {
    extern __shared__ __half sm2[];
    __shared__ int   s_entry[128];
    __shared__ float s_w[128];

    int tid = threadIdx.x, wid = tid >> 5, lane = tid & 31;
    int e = blockIdx.y;
    int base = g_off[e] + blockIdx.x * 128;
    int end  = g_off[e + 1];
    if (base >= end) return;

    __half* sH = sm2 + 17408;

    uint32_t uS  = smem_u32(sm2);
    uint32_t uX  = uS;
    uint32_t uH  = uS + 17408 * 2;
    uint32_t uW1 = uS + 2 * 17408 * 2;
    uint32_t uW2 = uS + 3 * 17408 * 2;

    for (int i = tid; i < 128; i += 512) {
        int p = base + i;
        if (p < end) {
            int en = g_perm[p];
            s_entry[i] = en;
            s_w[i] = g_top_w[en];
        } else {
            s_entry[i] = -1;
            s_w[i] = 0.0f;
        }
    }
    __syncthreads();

    const __half* W1 = E1c + e * (SD_ * HR_);
    const __half* W2 = E2c + e * (HR_ * SD_);
    const float* b1 = be1 + e * HR_;
    const float* b2 = be2 + e * SD_;

    // X gather (zero-fill masked rows): 128 rows x 16 chunks
    for (int i = tid; i < 2048; i += 512) {
        int row = i >> 4, u = i & 15;
        int en = s_entry[row];
        int sz = (en >= 0) ? 16 : 0;
        int slot = en >> 1;
        long goff = (en >= 0) ? ((long)(slot >> 3) * DIM_ + (slot & 7) * SD_ + u * 8) : 0;
        cp16(uX + (uint32_t)(row * 136 + u * 8) * 2, Xc + goff, sz);
    }
    // W1 chunk 0: [k=128][h=128]
    for (int i = tid; i < 2048; i += 512) {
        int k = i >> 4, u = i & 15;
        cp16(uW1 + (uint32_t)(k * 136 + u * 8) * 2, W1 + k * HR_ + u * 8, 16);
    }
    cp_commit();
    cp_wait0();
    __syncthreads();

    int wm = wid & 3, wn = wid >> 2;
    int lo16 = lane & 15, hi16 = lane >> 4;
    int row_in = lane >> 2, colq = (lane & 3) * 2;

    float yacc[2][4][4];
#pragma unroll
    for (int i = 0; i < 2; i++)
#pragma unroll
        for (int j = 0; j < 4; j++)
#pragma unroll
            for (int q = 0; q < 4; q++) yacc[i][j][q] = 0.0f;

    for (int ch = 0; ch < 4; ch++) {
        int h0 = ch * 128;

        // prefetch W2[ch] during GEMM1: [k=128 hidden][d=128]
        for (int i = tid; i < 2048; i += 512) {
            int k = i >> 4, u = i & 15;
            cp16(uW2 + (uint32_t)(k * 136 + u * 8) * 2, W2 + (h0 + k) * SD_ + u * 8, 16);
        }
        cp_commit();

        // GEMM1: H = X @ W1[ch]  (M=128, N=128, K=128)
        float hacc[2][4][4];
#pragma unroll
        for (int i = 0; i < 2; i++)
#pragma unroll
            for (int j = 0; j < 4; j++)
#pragma unroll
                for (int q = 0; q < 4; q++) hacc[i][j][q] = 0.0f;

#pragma unroll
        for (int ks = 0; ks < 8; ks++) {
            int k0 = ks * 16;
            uint32_t Bf[4][2];
#pragma unroll
            for (int p = 0; p < 2; p++) {
                uint32_t boff = (uint32_t)(((k0 + lo16) * 136 + wn * 32 + p * 16 + 8 * hi16) * 2);
                uint32_t r4[4];
                ldsm_x4_t(r4, uW1 + boff);
                Bf[p * 2][0] = r4[0]; Bf[p * 2][1] = r4[1];
                Bf[p * 2 + 1][0] = r4[2]; Bf[p * 2 + 1][1] = r4[3];
            }
            uint32_t Af[2][4];
#pragma unroll
            for (int mt = 0; mt < 2; mt++) {
                uint32_t aoff = (uint32_t)(((wm * 32 + mt * 16 + lo16) * 136 + k0 + 8 * hi16) * 2);
                ldsm_x4(Af[mt], uX + aoff);
            }
#pragma unroll
            for (int mt = 0; mt < 2; mt++)
#pragma unroll
                for (int nt = 0; nt < 4; nt++) mma_f16(hacc[mt][nt], Af[mt], Bf[nt]);
        }

        // H epilogue: gelu(bias+acc) -> fp16 into sH
#pragma unroll
        for (int mt = 0; mt < 2; mt++) {
#pragma unroll
            for (int nt = 0; nt < 4; nt++) {
                int n0 = wn * 32 + nt * 8 + colq;
                float bb0 = b1[h0 + n0], bb1 = b1[h0 + n0 + 1];
                int r0 = wm * 32 + mt * 16 + row_in;
                *(__half2*)(sH + r0 * 136 + n0) =
                    __floats2half2_rn(gelu_t(hacc[mt][nt][0] + bb0), gelu_t(hacc[mt][nt][1] + bb1));
                *(__half2*)(sH + (r0 + 8) * 136 + n0) =
                    __floats2half2_rn(gelu_t(hacc[mt][nt][2] + bb0), gelu_t(hacc[mt][nt][3] + bb1));
            }
        }
        cp_wait0();
        __syncthreads();

        // prefetch W1[ch+1] during GEMM2
        if (ch < 3) {
            int h1 = h0 + 128;
            for (int i = tid; i < 2048; i += 512) {
                int k = i >> 4, u = i & 15;
                cp16(uW1 + (uint32_t)(k * 136 + u * 8) * 2, W1 + k * HR_ + h1 + u * 8, 16);
            }
        }
        cp_commit();

        // GEMM2: Y += H @ W2[ch]  (M=128, N=128, K=128)
#pragma unroll
        for (int ks = 0; ks < 8; ks++) {
            int k0 = ks * 16;
            uint32_t Bf[4][2];
#pragma unroll
            for (int p = 0; p < 2; p++) {
                uint32_t boff = (uint32_t)(((k0 + lo16) * 136 + wn * 32 + p * 16 + 8 * hi16) * 2);
                uint32_t r4[4];
                ldsm_x4_t(r4, uW2 + boff);
                Bf[p * 2][0] = r4[0]; Bf[p * 2][1] = r4[1];
                Bf[p * 2 + 1][0] = r4[2]; Bf[p * 2 + 1][1] = r4[3];
            }
            uint32_t Af[2][4];
#pragma unroll
            for (int mt = 0; mt < 2; mt++) {
                uint32_t aoff = (uint32_t)(((wm * 32 + mt * 16 + lo16) * 136 + k0 + 8 * hi16) * 2);
                ldsm_x4(Af[mt], uH + aoff);
            }
#pragma unroll
            for (int mt = 0; mt < 2; mt++)
#pragma unroll
                for (int nt = 0; nt < 4; nt++) mma_f16(yacc[mt][nt], Af[mt], Bf[nt]);
        }
        cp_wait0();
        __syncthreads();
    }

    // epilogue: red.add w*(y+b2) directly into out
#pragma unroll
    for (int mt = 0; mt < 2; mt++) {
#pragma unroll
        for (int nt = 0; nt < 4; nt++) {
            int n0 = wn * 32 + nt * 8 + colq;
            float bb0 = b2[n0], bb1 = b2[n0 + 1];
            int r0 = wm * 32 + mt * 16 + row_in;
            int en0 = s_entry[r0];
            if (en0 >= 0) {
                float w = s_w[r0];
                int slot = en0 >> 1;
                float* dst = out + (slot >> 3) * DIM_ + (slot & 7) * SD_ + n0;
                red_add(dst, w * (yacc[mt][nt][0] + bb0));
                red_add(dst + 1, w * (yacc[mt][nt][1] + bb1));
            }
            int en1 = s_entry[r0 + 8];
            if (en1 >= 0) {
                float w = s_w[r0 + 8];
                int slot = en1 >> 1;
                float* dst = out + (slot >> 3) * DIM_ + (slot & 7) * SD_ + n0;
                red_add(dst, w * (yacc[mt][nt][2] + bb0));
                red_add(dst + 1, w * (yacc[mt][nt][3] + bb1));
            }
        }
    }
}

// ---------------- init ----------------
__global__ void init_kernel() {
    int t = threadIdx.x;
    if (t < NE_) { g_cnt[t] = 0; g_wsum[t] = 0.0f; }
}

// ---------------- router ----------------
__global__ void router_kernel(const float* __restrict__ X, const float* __restrict__ Wr) {
    __shared__ float Wrs[SD_ * NE_];
    __shared__ int   scnt[NE_];
    __shared__ float sws[NE_];
    int tid = threadIdx.x;
    for (int i = tid; i < SD_ * NE_; i += 128) Wrs[i] = Wr[i];
    if (tid < NE_) { scnt[tid] = 0; sws[tid] = 0.0f; }
    __syncthreads();

    int slot = blockIdx.x * 128 + tid;
    const float* x = X + (slot >> 3) * DIM_ + (slot & 7) * SD_;
    float lg[NE_];
#pragma unroll
    for (int e = 0; e < NE_; e++) lg[e] = 0.0f;
    for (int k = 0; k < SD_; k++) {
        float xv = x[k];
        const float* wr = &Wrs[k * NE_];
#pragma unroll
        for (int e = 0; e < NE_; e++) lg[e] += xv * wr[e];
    }
    float mx = lg[0];
#pragma unroll
    for (int e = 1; e < NE_; e++) mx = fmaxf(mx, lg[e]);
    float p[NE_]; float sum = 0.0f;
#pragma unroll
    for (int e = 0; e < NE_; e++) { p[e] = expf(lg[e] - mx); sum += p[e]; }
    float inv = 1.0f / sum;
    int i0 = 0; float m0 = -1.0f;
#pragma unroll
    for (int e = 0; e < NE_; e++) if (p[e] > m0) { m0 = p[e]; i0 = e; }
    int i1 = 0; float m1 = -1.0f;
#pragma unroll
    for (int e = 0; e < NE_; e++) if (e != i0 && p[e] > m1) { m1 = p[e]; i1 = e; }
    float w0 = m0 * inv, w1 = m1 * inv;

    g_top_idx[2 * slot]     = i0;
    g_top_idx[2 * slot + 1] = i1;
    g_top_w[2 * slot]       = w0;
    g_top_w[2 * slot + 1]   = w1;

    atomicAdd(&scnt[i0], 1); atomicAdd(&scnt[i1], 1);
    atomicAdd(&sws[i0], w0); atomicAdd(&sws[i1], w1);
    __syncthreads();
    if (tid < NE_) {
        atomicAdd(&g_cnt[tid], scnt[tid]);
        atomicAdd(&g_wsum[tid], sws[tid]);
    }
}

// ---------------- offsets + aux (writes aux into zeroed out) ----------------
__global__ void offsets_kernel(float* __restrict__ out, int out_size) {
    if (threadIdx.x == 0) {
        int acc = 0; float aux = 0.0f;
        for (int e = 0; e < NE_; e++) {
            g_off[e] = acc; g_cursor[e] = acc;
            acc += g_cnt[e];
            float f = (float)g_cnt[e] / ((float)NS_ * (float)KTOP_);
            float P = g_wsum[e] / (float)NS_;
            aux += f * P;
        }
        g_off[NE_] = acc;
        if (out_size > TOK_ * DIM_) out[TOK_ * DIM_] = (float)NE_ * aux;
    }
}

// ---------------- scatter ----------------
__global__ void scatter_kernel() {
    int slot = blockIdx.x * blockDim.x + threadIdx.x;
    if (slot >= NS_) return;
#pragma unroll
    for (int k = 0; k < KTOP_; k++) {
        int en = 2 * slot + k;
        int e = g_top_idx[en];
        int p = atomicAdd(&g_cursor[e], 1);
        g_perm[p] = en;
    }
}

// ---------------- launch ----------------
extern "C" void kernel_launch(void* const* d_in, const int* in_sizes, int n_in,
                              void* d_out, int out_size) {
    const float* X   = (const float*)d_in[0];
    const float* Ws1 = (const float*)d_in[1];
    const float* bs1 = (const float*)d_in[2];
    const float* Ws2 = (const float*)d_in[3];
    const float* bs2 = (const float*)d_in[4];
    const float* Wr  = (const float*)d_in[5];
    const float* We1 = (const float*)d_in[6];
    const float* be1 = (const float*)d_in[7];
    const float* We2 = (const float*)d_in[8];
    const float* be2 = (const float*)d_in[9];
    float* out = (float*)d_out;

    static cudaStream_t s2 = nullptr, s3 = nullptr;
    static cudaEvent_t evStart = nullptr, evScatter = nullptr, evX = nullptr;
    static cudaEvent_t evJoin = nullptr, evZero = nullptr;
    if (s2 == nullptr) {
        cudaStreamCreateWithFlags(&s2, cudaStreamNonBlocking);
        cudaStreamCreateWithFlags(&s3, cudaStreamNonBlocking);
        cudaEventCreateWithFlags(&evStart,   cudaEventDisableTiming);
        cudaEventCreateWithFlags(&evScatter, cudaEventDisableTiming);
        cudaEventCreateWithFlags(&evX,       cudaEventDisableTiming);
        cudaEventCreateWithFlags(&evJoin,    cudaEventDisableTiming);
        cudaEventCreateWithFlags(&evZero,    cudaEventDisableTiming);
    }

    cudaFuncSetAttribute(gemm_hmma<0>, cudaFuncAttributeMaxDynamicSharedMemorySize, GSM_BYTES);
    cudaFuncSetAttribute(gemm_hmma<1>, cudaFuncAttributeMaxDynamicSharedMemorySize, GSM_BYTES);
    cudaFuncSetAttribute(routed_hmma, cudaFuncAttributeMaxDynamicSharedMemorySize, RT2_SMEM);

    __half *Xc, *W1c, *W2c, *H1c, *E1c, *E2c;
    cudaGetSymbolAddress((void**)&Xc,  g_Xc);
    cudaGetSymbolAddress((void**)&W1c, g_W1c);
    cudaGetSymbolAddress((void**)&W2c, g_W2c);
    cudaGetSymbolAddress((void**)&H1c, g_H1c);
    cudaGetSymbolAddress((void**)&E1c, g_E1c);
    cudaGetSymbolAddress((void**)&E2c, g_E2c);

    // ---- main: zero the output first ----
    zero_kernel<<<(out_size / 4 + 255) / 256, 256>>>(out, out_size);
    cudaEventRecord(evZero, 0);

    // ---- fork: three streams ----
    cudaEventRecord(evStart, 0);
    cudaStreamWaitEvent(s2, evStart, 0);
    cudaStreamWaitEvent(s3, evZero, 0);

    // s3: router chain (off the critical path)
    init_kernel<<<1, 64, 0, s3>>>();
    router_kernel<<<NS_ / 128, 128, 0, s3>>>(X, Wr);
    offsets_kernel<<<1, 32, 0, s3>>>(out, out_size);
    scatter_kernel<<<NS_ / 128, 128, 0, s3>>>();
    cudaEventRecord(evScatter, s3);

    // s2: routed prerequisites + routed
    cvt_kernel<<<(TOK_ * DIM_ / 4 + 255) / 256, 256, 0, s2>>>(X, Xc, TOK_ * DIM_ / 4);
    cudaEventRecord(evX, s2);
    cvt2_kernel<<<(NE_ * SD_ * HR_ / 4 + NE_ * HR_ * SD_ / 4 + 255) / 256, 256, 0, s2>>>(
        We1, E1c, NE_ * SD_ * HR_ / 4, We2, E2c, NE_ * HR_ * SD_ / 4);
    cudaStreamWaitEvent(s2, evScatter, 0);
    routed_hmma<<<dim3(NENT_ / 128, NE_), 512, RT2_SMEM, s2>>>(
        Xc, E1c, be1, E2c, be2, out);
    cudaEventRecord(evJoin, s2);

    // main: shared expert (critical path); gemm2 red.adds into zeroed out
    cvt2_kernel<<<(DIM_ * HSH_ / 4 + HSH_ * DIM_ / 4 + 255) / 256, 256>>>(
        Ws1, W1c, DIM_ * HSH_ / 4, Ws2, W2c, HSH_ * DIM_ / 4);
    cudaStreamWaitEvent(0, evX, 0);
    gemm_hmma<0><<<dim3(HSH_ / BN_, TOK_ / BM_), 256, GSM_BYTES>>>(
        Xc, W1c, bs1, nullptr, H1c, TOK_, HSH_, DIM_);
    gemm_hmma<1><<<dim3(DIM_ / BN_, TOK_ / BM_), 256, GSM_BYTES>>>(
        H1c, W2c, bs2, out, nullptr, TOK_, DIM_, HSH_);

    // ---- join ----
    cudaStreamWaitEvent(0, evJoin, 0);
}

// round 16
// speedup vs baseline: 1.6478x; 1.0136x over previous
#include <cuda_runtime.h>
#include <cuda_fp16.h>
#include <cstdint>

// ---------------- problem constants ----------------
#define B_ 2
#define T_ 2048
#define DIM_ 1024
#define SEG_ 8
#define SD_ 128
#define NE_ 16
#define KTOP_ 2
#define HSH_ 4096
#define HR_ 512
#define TOK_ (B_ * T_)            // 4096 tokens
#define NS_ (TOK_ * SEG_)         // 32768 token-segments
#define NENT_ (NS_ * KTOP_)       // 65536 routed entries

// ---------------- device scratch ----------------
__device__ __half g_Xc[TOK_ * DIM_];
__device__ __half g_W1c[DIM_ * HSH_];
__device__ __half g_W2c[HSH_ * DIM_];
__device__ __half g_H1c[TOK_ * HSH_];
__device__ __half g_E1c[NE_ * SD_ * HR_];
__device__ __half g_E2c[NE_ * HR_ * SD_];
__device__ int   g_top_idx[NENT_];
__device__ float g_top_w[NENT_];
__device__ int   g_cnt[NE_];
__device__ float g_wsum[NE_];
__device__ int   g_off[NE_ + 1];
__device__ int   g_cursor[NE_];
__device__ int   g_perm[NENT_];

__device__ __forceinline__ float gelu_t(float x) {
    float x3 = x * x * x;
    return 0.5f * x * (1.0f + tanhf(0.7978845608028654f * (x + 0.044715f * x3)));
}

__device__ __forceinline__ uint32_t smem_u32(const void* p) {
    uint32_t a;
    asm("{ .reg .u64 t; cvta.to.shared.u64 t, %1; cvt.u32.u64 %0, t; }" : "=r"(a) : "l"(p));
    return a;
}

__device__ __forceinline__ void ldsm_x4(uint32_t r[4], uint32_t addr) {
    asm volatile("ldmatrix.sync.aligned.m8n8.x4.shared.b16 {%0,%1,%2,%3}, [%4];"
        : "=r"(r[0]), "=r"(r[1]), "=r"(r[2]), "=r"(r[3]) : "r"(addr));
}
__device__ __forceinline__ void ldsm_x4_t(uint32_t r[4], uint32_t addr) {
    asm volatile("ldmatrix.sync.aligned.m8n8.x4.trans.shared.b16 {%0,%1,%2,%3}, [%4];"
        : "=r"(r[0]), "=r"(r[1]), "=r"(r[2]), "=r"(r[3]) : "r"(addr));
}
__device__ __forceinline__ void mma_f16(float d[4], const uint32_t a[4], const uint32_t b[2]) {
    asm volatile("mma.sync.aligned.m16n8k16.row.col.f32.f16.f16.f32 "
        "{%0,%1,%2,%3}, {%4,%5,%6,%7}, {%8,%9}, {%0,%1,%2,%3};"
        : "+f"(d[0]), "+f"(d[1]), "+f"(d[2]), "+f"(d[3])
        : "r"(a[0]), "r"(a[1]), "r"(a[2]), "r"(a[3]), "r"(b[0]), "r"(b[1]));
}
__device__ __forceinline__ void cp16(uint32_t s, const void* g, int szbytes) {
    asm volatile("cp.async.cg.shared.global [%0], [%1], 16, %2;"
        :: "r"(s), "l"(g), "r"(szbytes));
}
__device__ __forceinline__ void cp_commit() { asm volatile("cp.async.commit_group;" ::: "memory"); }
__device__ __forceinline__ void cp_wait0()  { asm volatile("cp.async.wait_group 0;" ::: "memory"); }
__device__ __forceinline__ void cp_wait1()  { asm volatile("cp.async.wait_group 1;" ::: "memory"); }
__device__ __forceinline__ void red_add(float* p, float v) {
    asm volatile("red.global.add.f32 [%0], %1;" :: "l"(p), "f"(v) : "memory");
}

// ---------------- zero output ----------------
__global__ void zero_kernel(float* __restrict__ out, int out_size) {
    int i = blockIdx.x * 256 + threadIdx.x;
    int n4 = out_size >> 2;
    if (i < n4) ((float4*)out)[i] = make_float4(0.f, 0.f, 0.f, 0.f);
    if (i == 0)
        for (int j = n4 * 4; j < out_size; j++) out[j] = 0.0f;
}

// ---------------- fp32 -> fp16 conversion ----------------
__global__ void cvt_kernel(const float* __restrict__ src, __half* __restrict__ dst, int n4) {
    int i = blockIdx.x * 256 + threadIdx.x;
    if (i >= n4) return;
    float4 v = ((const float4*)src)[i];
    ((__half2*)dst)[2 * i]     = __floats2half2_rn(v.x, v.y);
    ((__half2*)dst)[2 * i + 1] = __floats2half2_rn(v.z, v.w);
}

__global__ void cvt2_kernel(const float* __restrict__ s1, __half* __restrict__ d1, int n1,
                            const float* __restrict__ s2, __half* __restrict__ d2, int n2) {
    int i = blockIdx.x * 256 + threadIdx.x;
    const float* s; __half* d; int j;
    if (i < n1) { s = s1; d = d1; j = i; }
    else if (i < n1 + n2) { s = s2; d = d2; j = i - n1; }
    else return;
    float4 v = ((const float4*)s)[j];
    ((__half2*)d)[2 * j]     = __floats2half2_rn(v.x, v.y);
    ((__half2*)d)[2 * j + 1] = __floats2half2_rn(v.z, v.w);
}

// ---------------- HMMA fp16 GEMM, 3-stage cp.async pipeline ----------------
// MODE 0: epilogue gelu(acc+bias) -> Ch fp16
// MODE 1: epilogue red.add(acc+bias) into Cf fp32
#define BM_ 128
#define BN_ 128
#define BK_ 64
#define ASTR_ 72
#define BSTR_ 136
#define STG_BYTES 35840
#define GSM_BYTES (3 * STG_BYTES)

template <int MODE>
__global__ void __launch_bounds__(256, 2)
gemm_hmma(const __half* __restrict__ A, const __half* __restrict__ Bm,
          const float* __restrict__ bias,
          float* __restrict__ Cf, __half* __restrict__ Ch,
          int M, int N, int K) {
    extern __shared__ char smraw[];

    int tid = threadIdx.x;
    int wid = tid >> 5, lane = tid & 31;
    int wm = wid & 1, wn = wid >> 1;
    int bn = blockIdx.x * BN_, bm = blockIdx.y * BM_;

    uint32_t uS = smem_u32(smraw);

    float acc[4][4][4];
#pragma unroll
    for (int i = 0; i < 4; i++)
#pragma unroll
        for (int j = 0; j < 4; j++)
#pragma unroll
            for (int q = 0; q < 4; q++) acc[i][j][q] = 0.0f;

    int lo16 = lane & 15, hi16 = lane >> 4;

    auto load_chunk = [&](int kc, int st) {
        uint32_t bA = uS + st * STG_BYTES;
        uint32_t bB = bA + 18432;
#pragma unroll 2
        for (int i = tid; i < 1024; i += 256) {
            int r = i >> 3, u = i & 7;
            int g = (bm + r) * K + kc + u * 8;
            cp16(bA + (uint32_t)(r * ASTR_ + u * 8) * 2, A + g, 16);
        }
#pragma unroll 2
        for (int i = tid; i < 1024; i += 256) {
            int r = i >> 4, u = i & 15;
            int g = (kc + r) * N + bn + u * 8;
            cp16(bB + (uint32_t)(r * BSTR_ + u * 8) * 2, Bm + g, 16);
        }
    };

    int nch = K / BK_;
    load_chunk(0, 0);
    cp_commit();
    load_chunk(BK_, 1);
    cp_commit();

    for (int c = 0; c < nch; c++) {
        int st = c % 3;
        cp_wait1();
        __syncthreads();
        if (c + 2 < nch) load_chunk((c + 2) * BK_, (c + 2) % 3);
        cp_commit();

        uint32_t uA = uS + st * STG_BYTES;
        uint32_t uB = uA + 18432;

#pragma unroll
        for (int ks = 0; ks < 4; ks++) {
            int k0 = ks * 16;
            uint32_t Bf[4][2];
#pragma unroll
            for (int p = 0; p < 2; p++) {
                uint32_t boff = (uint32_t)(((k0 + lo16) * BSTR_ + wn * 32 + p * 16 + 8 * hi16) * 2);
                uint32_t r4[4];
                ldsm_x4_t(r4, uB + boff);
                Bf[p * 2][0] = r4[0]; Bf[p * 2][1] = r4[1];
                Bf[p * 2 + 1][0] = r4[2]; Bf[p * 2 + 1][1] = r4[3];
            }
            uint32_t Af[4][4];
#pragma unroll
            for (int mt = 0; mt < 4; mt++) {
                uint32_t aoff = (uint32_t)(((wm * 64 + mt * 16 + lo16) * ASTR_ + k0 + 8 * hi16) * 2);
                ldsm_x4(Af[mt], uA + aoff);
            }
#pragma unroll
            for (int mt = 0; mt < 4; mt++)
#pragma unroll
                for (int nt = 0; nt < 4; nt++) mma_f16(acc[mt][nt], Af[mt], Bf[nt]);
        }
    }

    int row_in = lane >> 2, colq = (lane & 3) * 2;
#pragma unroll
    for (int mt = 0; mt < 4; mt++) {
#pragma unroll
        for (int nt = 0; nt < 4; nt++) {
            int m0 = bm + wm * 64 + mt * 16 + row_in;
            int n0 = bn + wn * 32 + nt * 8 + colq;
            float b0 = bias[n0], b1 = bias[n0 + 1];
            float v00 = acc[mt][nt][0] + b0, v01 = acc[mt][nt][1] + b1;
            float v10 = acc[mt][nt][2] + b0, v11 = acc[mt][nt][3] + b1;
            if (MODE == 0) {
                *(__half2*)(Ch + m0 * N + n0)       = __floats2half2_rn(gelu_t(v00), gelu_t(v01));
                *(__half2*)(Ch + (m0 + 8) * N + n0) = __floats2half2_rn(gelu_t(v10), gelu_t(v11));
            } else {
                red_add(Cf + m0 * N + n0, v00);
                red_add(Cf + m0 * N + n0 + 1, v01);
                red_add(Cf + (m0 + 8) * N + n0, v10);
                red_add(Cf + (m0 + 8) * N + n0 + 1, v11);
            }
        }
    }
}

// ---------------- routed experts: fp16, 512 threads, hidden chunks of 128 ----------------
#define RT2_SMEM (4 * 17408 * 2)

__global__ void __launch_bounds__(512)
routed_hmma(const __half* __restrict__ Xc,
            const __half* __restrict__ E1c, const float* __restrict__ be1,
            const __half* __restrict__ E2c, const float* __restrict__ be2,
            float* __restrict__ out) {
    extern __shared__ __half sm2[];
    __shared__ int   s_entry[128];
    __shared__ float s_w[128];

    int tid = threadIdx.x, wid = tid >> 5, lane = tid & 31;
    int e = blockIdx.y;
    int base = g_off[e] + blockIdx.x * 128;
    int end  = g_off[e + 1];
    if (base >= end) return;

    __half* sH = sm2 + 17408;

    uint32_t uS  = smem_u32(sm2);
    uint32_t uX  = uS;
    uint32_t uH  = uS + 17408 * 2;
    uint32_t uW1 = uS + 2 * 17408 * 2;
    uint32_t uW2 = uS + 3 * 17408 * 2;

    for (int i = tid; i < 128; i += 512) {
        int p = base + i;
        if (p < end) {
            int en = g_perm[p];
            s_entry[i] = en;
            s_w[i] = g_top_w[en];
        } else {
            s_entry[i] = -1;
            s_w[i] = 0.0f;
        }
    }
    __syncthreads();

    const __half* W1 = E1c + e * (SD_ * HR_);
    const __half* W2 = E2c + e * (HR_ * SD_);
    const float* b1 = be1 + e * HR_;
    const float* b2 = be2 + e * SD_;

    for (int i = tid; i < 2048; i += 512) {
        int row = i >> 4, u = i & 15;
        int en = s_entry[row];
        int sz = (en >= 0) ? 16 : 0;
        int slot = en >> 1;
        long goff = (en >= 0) ? ((long)(slot >> 3) * DIM_ + (slot & 7) * SD_ + u * 8) : 0;
        cp16(uX + (uint32_t)(row * 136 + u * 8) * 2, Xc + goff, sz);
    }
    for (int i = tid; i < 2048; i += 512) {
        int k = i >> 4, u = i & 15;
        cp16(uW1 + (uint32_t)(k * 136 + u * 8) * 2, W1 + k * HR_ + u * 8, 16);
    }
    cp_commit();
    cp_wait0();
    __syncthreads();

    int wm = wid & 3, wn = wid >> 2;
    int lo16 = lane & 15, hi16 = lane >> 4;
    int row_in = lane >> 2, colq = (lane & 3) * 2;

    float yacc[2][4][4];
#pragma unroll
    for (int i = 0; i < 2; i++)
#pragma unroll
        for (int j = 0; j < 4; j++)
#pragma unroll
            for (int q = 0; q < 4; q++) yacc[i][j][q] = 0.0f;

    for (int ch = 0; ch < 4; ch++) {
        int h0 = ch * 128;

        for (int i = tid; i < 2048; i += 512) {
            int k = i >> 4, u = i & 15;
            cp16(uW2 + (uint32_t)(k * 136 + u * 8) * 2, W2 + (h0 + k) * SD_ + u * 8, 16);
        }
        cp_commit();

        float hacc[2][4][4];
#pragma unroll
        for (int i = 0; i < 2; i++)
#pragma unroll
            for (int j = 0; j < 4; j++)
#pragma unroll
                for (int q = 0; q < 4; q++) hacc[i][j][q] = 0.0f;

#pragma unroll
        for (int ks = 0; ks < 8; ks++) {
            int k0 = ks * 16;
            uint32_t Bf[4][2];
#pragma unroll
            for (int p = 0; p < 2; p++) {
                uint32_t boff = (uint32_t)(((k0 + lo16) * 136 + wn * 32 + p * 16 + 8 * hi16) * 2);
                uint32_t r4[4];
                ldsm_x4_t(r4, uW1 + boff);
                Bf[p * 2][0] = r4[0]; Bf[p * 2][1] = r4[1];
                Bf[p * 2 + 1][0] = r4[2]; Bf[p * 2 + 1][1] = r4[3];
            }
            uint32_t Af[2][4];
#pragma unroll
            for (int mt = 0; mt < 2; mt++) {
                uint32_t aoff = (uint32_t)(((wm * 32 + mt * 16 + lo16) * 136 + k0 + 8 * hi16) * 2);
                ldsm_x4(Af[mt], uX + aoff);
            }
#pragma unroll
            for (int mt = 0; mt < 2; mt++)
#pragma unroll
                for (int nt = 0; nt < 4; nt++) mma_f16(hacc[mt][nt], Af[mt], Bf[nt]);
        }

#pragma unroll
        for (int mt = 0; mt < 2; mt++) {
#pragma unroll
            for (int nt = 0; nt < 4; nt++) {
                int n0 = wn * 32 + nt * 8 + colq;
                float bb0 = b1[h0 + n0], bb1 = b1[h0 + n0 + 1];
                int r0 = wm * 32 + mt * 16 + row_in;
                *(__half2*)(sH + r0 * 136 + n0) =
                    __floats2half2_rn(gelu_t(hacc[mt][nt][0] + bb0), gelu_t(hacc[mt][nt][1] + bb1));
                *(__half2*)(sH + (r0 + 8) * 136 + n0) =
                    __floats2half2_rn(gelu_t(hacc[mt][nt][2] + bb0), gelu_t(hacc[mt][nt][3] + bb1));
            }
        }
        cp_wait0();
        __syncthreads();

        if (ch < 3) {
            int h1 = h0 + 128;
            for (int i = tid; i < 2048; i += 512) {
                int k = i >> 4, u = i & 15;
                cp16(uW1 + (uint32_t)(k * 136 + u * 8) * 2, W1 + k * HR_ + h1 + u * 8, 16);
            }
        }
        cp_commit();

#pragma unroll
        for (int ks = 0; ks < 8; ks++) {
            int k0 = ks * 16;
            uint32_t Bf[4][2];
#pragma unroll
            for (int p = 0; p < 2; p++) {
                uint32_t boff = (uint32_t)(((k0 + lo16) * 136 + wn * 32 + p * 16 + 8 * hi16) * 2);
                uint32_t r4[4];
                ldsm_x4_t(r4, uW2 + boff);
                Bf[p * 2][0] = r4[0]; Bf[p * 2][1] = r4[1];
                Bf[p * 2 + 1][0] = r4[2]; Bf[p * 2 + 1][1] = r4[3];
            }
            uint32_t Af[2][4];
#pragma unroll
            for (int mt = 0; mt < 2; mt++) {
                uint32_t aoff = (uint32_t)(((wm * 32 + mt * 16 + lo16) * 136 + k0 + 8 * hi16) * 2);
                ldsm_x4(Af[mt], uH + aoff);
            }
#pragma unroll
            for (int mt = 0; mt < 2; mt++)
#pragma unroll
                for (int nt = 0; nt < 4; nt++) mma_f16(yacc[mt][nt], Af[mt], Bf[nt]);
        }
        cp_wait0();
        __syncthreads();
    }

#pragma unroll
    for (int mt = 0; mt < 2; mt++) {
#pragma unroll
        for (int nt = 0; nt < 4; nt++) {
            int n0 = wn * 32 + nt * 8 + colq;
            float bb0 = b2[n0], bb1 = b2[n0 + 1];
            int r0 = wm * 32 + mt * 16 + row_in;
            int en0 = s_entry[r0];
            if (en0 >= 0) {
                float w = s_w[r0];
                int slot = en0 >> 1;
                float* dst = out + (slot >> 3) * DIM_ + (slot & 7) * SD_ + n0;
                red_add(dst, w * (yacc[mt][nt][0] + bb0));
                red_add(dst + 1, w * (yacc[mt][nt][1] + bb1));
            }
            int en1 = s_entry[r0 + 8];
            if (en1 >= 0) {
                float w = s_w[r0 + 8];
                int slot = en1 >> 1;
                float* dst = out + (slot >> 3) * DIM_ + (slot & 7) * SD_ + n0;
                red_add(dst, w * (yacc[mt][nt][2] + bb0));
                red_add(dst + 1, w * (yacc[mt][nt][3] + bb1));
            }
        }
    }
}

// ---------------- init ----------------
__global__ void init_kernel() {
    int t = threadIdx.x;
    if (t < NE_) { g_cnt[t] = 0; g_wsum[t] = 0.0f; }
}

// ---------------- router ----------------
__global__ void router_kernel(const float* __restrict__ X, const float* __restrict__ Wr) {
    __shared__ float Wrs[SD_ * NE_];
    __shared__ int   scnt[NE_];
    __shared__ float sws[NE_];
    int tid = threadIdx.x;
    for (int i = tid; i < SD_ * NE_; i += 128) Wrs[i] = Wr[i];
    if (tid < NE_) { scnt[tid] = 0; sws[tid] = 0.0f; }
    __syncthreads();

    int slot = blockIdx.x * 128 + tid;
    const float* x = X + (slot >> 3) * DIM_ + (slot & 7) * SD_;
    float lg[NE_];
#pragma unroll
    for (int e = 0; e < NE_; e++) lg[e] = 0.0f;
    for (int k = 0; k < SD_; k++) {
        float xv = x[k];
        const float* wr = &Wrs[k * NE_];
#pragma unroll
        for (int e = 0; e < NE_; e++) lg[e] += xv * wr[e];
    }
    float mx = lg[0];
#pragma unroll
    for (int e = 1; e < NE_; e++) mx = fmaxf(mx, lg[e]);
    float p[NE_]; float sum = 0.0f;
#pragma unroll
    for (int e = 0; e < NE_; e++) { p[e] = expf(lg[e] - mx); sum += p[e]; }
    float inv = 1.0f / sum;
    int i0 = 0; float m0 = -1.0f;
#pragma unroll
    for (int e = 0; e < NE_; e++) if (p[e] > m0) { m0 = p[e]; i0 = e; }
    int i1 = 0; float m1 = -1.0f;
#pragma unroll
    for (int e = 0; e < NE_; e++) if (e != i0 && p[e] > m1) { m1 = p[e]; i1 = e; }
    float w0 = m0 * inv, w1 = m1 * inv;

    g_top_idx[2 * slot]     = i0;
    g_top_idx[2 * slot + 1] = i1;
    g_top_w[2 * slot]       = w0;
    g_top_w[2 * slot + 1]   = w1;

    atomicAdd(&scnt[i0], 1); atomicAdd(&scnt[i1], 1);
    atomicAdd(&sws[i0], w0); atomicAdd(&sws[i1], w1);
    __syncthreads();
    if (tid < NE_) {
        atomicAdd(&g_cnt[tid], scnt[tid]);
        atomicAdd(&g_wsum[tid], sws[tid]);
    }
}

// ---------------- offsets + aux (writes aux into zeroed out) ----------------
__global__ void offsets_kernel(float* __restrict__ out, int out_size) {
    if (threadIdx.x == 0) {
        int acc = 0; float aux = 0.0f;
        for (int e = 0; e < NE_; e++) {
            g_off[e] = acc; g_cursor[e] = acc;
            acc += g_cnt[e];
            float f = (float)g_cnt[e] / ((float)NS_ * (float)KTOP_);
            float P = g_wsum[e] / (float)NS_;
            aux += f * P;
        }
        g_off[NE_] = acc;
        if (out_size > TOK_ * DIM_) out[TOK_ * DIM_] = (float)NE_ * aux;
    }
}

// ---------------- scatter ----------------
__global__ void scatter_kernel() {
    int slot = blockIdx.x * blockDim.x + threadIdx.x;
    if (slot >= NS_) return;
#pragma unroll
    for (int k = 0; k < KTOP_; k++) {
        int en = 2 * slot + k;
        int e = g_top_idx[en];
        int p = atomicAdd(&g_cursor[e], 1);
        g_perm[p] = en;
    }
}

// ---------------- launch ----------------
extern "C" void kernel_launch(void* const* d_in, const int* in_sizes, int n_in,
                              void* d_out, int out_size) {
    const float* X   = (const float*)d_in[0];
    const float* Ws1 = (const float*)d_in[1];
    const float* bs1 = (const float*)d_in[2];
    const float* Ws2 = (const float*)d_in[3];
    const float* bs2 = (const float*)d_in[4];
    const float* Wr  = (const float*)d_in[5];
    const float* We1 = (const float*)d_in[6];
    const float* be1 = (const float*)d_in[7];
    const float* We2 = (const float*)d_in[8];
    const float* be2 = (const float*)d_in[9];
    float* out = (float*)d_out;

    static cudaStream_t s2 = nullptr, s3 = nullptr;
    static cudaEvent_t evStart = nullptr, evScatter = nullptr, evX = nullptr;
    static cudaEvent_t evJoin = nullptr, evZero = nullptr, evW2 = nullptr;
    if (s2 == nullptr) {
        cudaStreamCreateWithFlags(&s2, cudaStreamNonBlocking);
        cudaStreamCreateWithFlags(&s3, cudaStreamNonBlocking);
        cudaEventCreateWithFlags(&evStart,   cudaEventDisableTiming);
        cudaEventCreateWithFlags(&evScatter, cudaEventDisableTiming);
        cudaEventCreateWithFlags(&evX,       cudaEventDisableTiming);
        cudaEventCreateWithFlags(&evJoin,    cudaEventDisableTiming);
        cudaEventCreateWithFlags(&evZero,    cudaEventDisableTiming);
        cudaEventCreateWithFlags(&evW2,      cudaEventDisableTiming);
    }

    cudaFuncSetAttribute(gemm_hmma<0>, cudaFuncAttributeMaxDynamicSharedMemorySize, GSM_BYTES);
    cudaFuncSetAttribute(gemm_hmma<1>, cudaFuncAttributeMaxDynamicSharedMemorySize, GSM_BYTES);
    cudaFuncSetAttribute(routed_hmma, cudaFuncAttributeMaxDynamicSharedMemorySize, RT2_SMEM);

    __half *Xc, *W1c, *W2c, *H1c, *E1c, *E2c;
    cudaGetSymbolAddress((void**)&Xc,  g_Xc);
    cudaGetSymbolAddress((void**)&W1c, g_W1c);
    cudaGetSymbolAddress((void**)&W2c, g_W2c);
    cudaGetSymbolAddress((void**)&H1c, g_H1c);
    cudaGetSymbolAddress((void**)&E1c, g_E1c);
    cudaGetSymbolAddress((void**)&E2c, g_E2c);

    // ---- fork FIRST (stream 0 empty -> evStart fires immediately) ----
    cudaEventRecord(evStart, 0);
    cudaStreamWaitEvent(s2, evStart, 0);

    // main: zero output (gemm2/routed/aux all write into it)
    zero_kernel<<<(out_size / 4 + 255) / 256, 256>>>(out, out_size);
    cudaEventRecord(evZero, 0);
    cudaStreamWaitEvent(s3, evZero, 0);

    // s3: router chain (off the critical path; gated on zero for aux write)
    init_kernel<<<1, 64, 0, s3>>>();
    router_kernel<<<NS_ / 128, 128, 0, s3>>>(X, Wr);
    offsets_kernel<<<1, 32, 0, s3>>>(out, out_size);
    scatter_kernel<<<NS_ / 128, 128, 0, s3>>>();
    cudaEventRecord(evScatter, s3);

    // s2: X cvt -> W2 cvt (fills the wait-for-scatter window) -> expert cvts -> routed
    cvt_kernel<<<(TOK_ * DIM_ / 4 + 255) / 256, 256, 0, s2>>>(X, Xc, TOK_ * DIM_ / 4);
    cudaEventRecord(evX, s2);
    cvt_kernel<<<(HSH_ * DIM_ / 4 + 255) / 256, 256, 0, s2>>>(Ws2, W2c, HSH_ * DIM_ / 4);
    cudaEventRecord(evW2, s2);
    cvt2_kernel<<<(NE_ * SD_ * HR_ / 4 + NE_ * HR_ * SD_ / 4 + 255) / 256, 256, 0, s2>>>(
        We1, E1c, NE_ * SD_ * HR_ / 4, We2, E2c, NE_ * HR_ * SD_ / 4);
    cudaStreamWaitEvent(s2, evScatter, 0);
    routed_hmma<<<dim3(NENT_ / 128, NE_), 512, RT2_SMEM, s2>>>(
        Xc, E1c, be1, E2c, be2, out);
    cudaEventRecord(evJoin, s2);

    // main: shared expert; only W1 cvt on the critical path
    cvt_kernel<<<(DIM_ * HSH_ / 4 + 255) / 256, 256>>>(Ws1, W1c, DIM_ * HSH_ / 4);
    cudaStreamWaitEvent(0, evX, 0);
    gemm_hmma<0><<<dim3(HSH_ / BN_, TOK_ / BM_), 256, GSM_BYTES>>>(
        Xc, W1c, bs1, nullptr, H1c, TOK_, HSH_, DIM_);
    cudaStreamWaitEvent(0, evW2, 0);
    gemm_hmma<1><<<dim3(DIM_ / BN_, TOK_ / BM_), 256, GSM_BYTES>>>(
        H1c, W2c, bs2, out, nullptr, TOK_, DIM_, HSH_);

    // ---- join ----
    cudaStreamWaitEvent(0, evJoin, 0);
}